// round 12
// baseline (speedup 1.0000x reference)
#include <cuda_runtime.h>
#include <cuda_fp16.h>
#include <math.h>

#define NN   100000
#define EE   1600000
#define FIN  20
#define HH   128
#define EPSV 1e-5f
#define NTILES 782            // ceil(NN/128)

// ---------------- scratch ----------------
__device__ __align__(16) unsigned int g_yl16[NN * 64];   // fp16x2: [N][64] half2 = 128 ch
__device__ __align__(16) float g_yr[NN * HH];
__device__ __align__(16) float g_pre[NN * HH];
__device__ __align__(16) float g_a20[NN * FIN];
__device__ int   g_deg[NN];
__device__ int   g_off[NN + 1];
__device__ int   g_csr[EE];
__device__ int   g_bsum[128];
__device__ float g_stats[3][2 * HH];

typedef unsigned long long ull;
typedef unsigned int uint;

__device__ __forceinline__ ull pk2(float lo, float hi) {
    ull r; asm("mov.b64 %0, {%1,%2};" : "=l"(r) : "f"(lo), "f"(hi)); return r;
}
__device__ __forceinline__ void upk2(ull v, float& lo, float& hi) {
    asm("mov.b64 {%0,%1}, %2;" : "=f"(lo), "=f"(hi) : "l"(v));
}
__device__ __forceinline__ void fma2(ull& d, ull a, ull b) {
    asm("fma.rn.f32x2 %0, %1, %2, %0;" : "+l"(d) : "l"(a), "l"(b));
}
__device__ __forceinline__ float gelu_f(float x) {
    return 0.5f * x * (1.0f + erff(x * 0.70710678118654752f));
}
__device__ __forceinline__ uint pack_h2(float lo, float hi) {
    uint r; asm("cvt.rn.f16x2.f32 %0, %2, %1;" : "=r"(r) : "f"(lo), "f"(hi)); return r;
}
__device__ __forceinline__ void mma_f16(float* d, uint a0, uint a1, uint a2, uint a3,
                                        uint b0, uint b1) {
    asm volatile(
        "mma.sync.aligned.m16n8k16.row.col.f32.f16.f16.f32 "
        "{%0,%1,%2,%3}, {%4,%5,%6,%7}, {%8,%9}, {%0,%1,%2,%3};"
        : "+f"(d[0]), "+f"(d[1]), "+f"(d[2]), "+f"(d[3])
        : "r"(a0), "r"(a1), "r"(a2), "r"(a3), "r"(b0), "r"(b1));
}

// ---------------- init + CSR build ----------------
__global__ void k_init() {
    int i = blockIdx.x * blockDim.x + threadIdx.x;
    if (i < NN) g_deg[i] = 0;
    if (i < 3 * 2 * HH) ((float*)g_stats)[i] = 0.f;
}
__global__ void k_hist(const int* __restrict__ ei) {
    int e = blockIdx.x * blockDim.x + threadIdx.x;
    if (e < EE) atomicAdd(&g_deg[ei[EE + e]], 1);
}
// warp-shuffle scan over 1024 elements: 3 phases, few barriers
__global__ void k_scan1() {
    __shared__ int wsum[32];
    int t = threadIdx.x;
    int lane = t & 31, wp = t >> 5;
    int i = blockIdx.x * 1024 + t;
    int v = (i < NN) ? g_deg[i] : 0;
    // warp inclusive scan
    int sc = v;
#pragma unroll
    for (int d = 1; d < 32; d <<= 1) {
        int x = __shfl_up_sync(0xffffffffu, sc, d);
        if (lane >= d) sc += x;
    }
    if (lane == 31) wsum[wp] = sc;
    __syncthreads();
    if (wp == 0) {
        int w = wsum[lane];
#pragma unroll
        for (int d = 1; d < 32; d <<= 1) {
            int x = __shfl_up_sync(0xffffffffu, w, d);
            if (lane >= d) w += x;
        }
        wsum[lane] = w;
    }
    __syncthreads();
    int total = sc + (wp > 0 ? wsum[wp - 1] : 0);
    if (i < NN) g_off[i + 1] = total;
    if (t == 1023) g_bsum[blockIdx.x] = total;
}
// merged scan2+scan3 (verified): all 256 threads reach every barrier.
__global__ void k_scan3(int nb) {
    __shared__ int ex[128];
    int t = threadIdx.x;
    int run = 0;
    if (t < 128) {
        run = (t < nb) ? g_bsum[t] : 0;
        ex[t] = run;
    }
    __syncthreads();
#pragma unroll
    for (int d = 1; d < 128; d <<= 1) {
        int x = 0;
        if (t < 128 && t >= d) x = ex[t - d];
        __syncthreads();
        if (t < 128) ex[t] += x;
        __syncthreads();
    }
    if (t < 128) ex[t] -= run;   // exclusive
    __syncthreads();
    int i = blockIdx.x * blockDim.x + t;
    if (i < NN) {
        int tot = g_off[i + 1] + ex[i >> 10];
        g_off[i + 1] = tot;
        int d = g_deg[i];
        g_deg[i] = tot - d;
        if (i == 0) g_off[0] = 0;
    }
}
__global__ void k_fill(const int* __restrict__ ei) {
    int e = blockIdx.x * blockDim.x + threadIdx.x;
    if (e < EE) {
        int d = ei[EE + e];
        int pos = atomicAdd(&g_deg[d], 1);
        g_csr[pos] = ei[e];
    }
}

// ---------------- layer-0 aggregation (20 cols, 1 warp/node) ----------------
__global__ void k_agg20(const float* __restrict__ x) {
    int w = (blockIdx.x * blockDim.x + threadIdx.x) >> 5;
    int lane = threadIdx.x & 31;
    if (w >= NN) return;
    int off = g_off[w], end = g_off[w + 1];
    float acc = 0.f;
    for (int j = off; j < end; j += 32) {
        int idx = (j + lane < end) ? g_csr[j + lane] : 0;
        int cnt = min(32, end - j);
        int t = 0;
        for (; t + 4 <= cnt; t += 4) {
            int s0 = __shfl_sync(0xffffffffu, idx, t);
            int s1 = __shfl_sync(0xffffffffu, idx, t + 1);
            int s2 = __shfl_sync(0xffffffffu, idx, t + 2);
            int s3 = __shfl_sync(0xffffffffu, idx, t + 3);
            if (lane < FIN) {
                float v0 = x[s0 * FIN + lane], v1 = x[s1 * FIN + lane];
                float v2 = x[s2 * FIN + lane], v3 = x[s3 * FIN + lane];
                acc += (v0 + v1) + (v2 + v3);
            }
        }
        for (; t < cnt; t++) {
            int s = __shfl_sync(0xffffffffu, idx, t);
            if (lane < FIN) acc += x[s * FIN + lane];
        }
    }
    if (lane < FIN) {
        int deg = end - off;
        g_a20[w * FIN + lane] = acc * (deg > 0 ? 1.f / (float)deg : 0.f);
    }
}

// ---------------- layer-0 GEMM (K=20) + bias + stats ----------------
__global__ __launch_bounds__(256) void k_gemm0(
    const float* __restrict__ x, const float* __restrict__ Wl,
    const float* __restrict__ bl, const float* __restrict__ Wr)
{
    __shared__ float Wls[FIN][HH], Wrs[FIN][HH], bls[HH];
    __shared__ float As[64][FIN + 1], Xs[64][FIN + 1];
    __shared__ float red[16][HH];
    int tid = threadIdx.x;
    for (int e = tid; e < HH * FIN; e += 256) {
        int o = e / FIN, k = e % FIN;
        Wls[k][o] = Wl[e];
        Wrs[k][o] = Wr[e];
    }
    if (tid < HH) bls[tid] = bl[tid];
    int n0 = blockIdx.x * 64;
    for (int e = tid; e < 64 * FIN; e += 256) {
        int i = e / FIN, k = e % FIN;
        int n = n0 + i;
        As[i][k] = (n < NN) ? g_a20[n * FIN + k] : 0.f;
        Xs[i][k] = (n < NN) ? x[n * FIN + k] : 0.f;
    }
    __syncthreads();
    int tm = tid >> 4, tn = tid & 15;
    ull acc[4][4];
#pragma unroll
    for (int r = 0; r < 4; r++)
#pragma unroll
        for (int c = 0; c < 4; c++)
            acc[r][c] = pk2(bls[tn * 8 + 2 * c], bls[tn * 8 + 2 * c + 1]);
#pragma unroll 4
    for (int k = 0; k < FIN; k++) {
        const ull* wl = (const ull*)&Wls[k][tn * 8];
        const ull* wr = (const ull*)&Wrs[k][tn * 8];
#pragma unroll
        for (int r = 0; r < 4; r++) {
            ull a2 = pk2(As[tm * 4 + r][k], As[tm * 4 + r][k]);
            ull x2 = pk2(Xs[tm * 4 + r][k], Xs[tm * 4 + r][k]);
#pragma unroll
            for (int c = 0; c < 4; c++) { fma2(acc[r][c], a2, wl[c]); fma2(acc[r][c], x2, wr[c]); }
        }
    }
    float av[4][8];
    float s[8] = {0,0,0,0,0,0,0,0}, s2[8] = {0,0,0,0,0,0,0,0};
#pragma unroll
    for (int r = 0; r < 4; r++) {
#pragma unroll
        for (int c = 0; c < 4; c++) upk2(acc[r][c], av[r][2 * c], av[r][2 * c + 1]);
        int n = n0 + tm * 4 + r;
        if (n < NN) {
            float4* o4 = (float4*)(g_pre + n * HH + tn * 8);
            o4[0] = make_float4(av[r][0], av[r][1], av[r][2], av[r][3]);
            o4[1] = make_float4(av[r][4], av[r][5], av[r][6], av[r][7]);
#pragma unroll
            for (int j = 0; j < 8; j++) { s[j] += av[r][j]; s2[j] += av[r][j] * av[r][j]; }
        }
    }
#pragma unroll
    for (int j = 0; j < 8; j++) red[tm][tn * 8 + j] = s[j];
    __syncthreads();
    if (tid < HH) {
        float t = 0.f;
#pragma unroll
        for (int w = 0; w < 16; w++) t += red[w][tid];
        atomicAdd(&g_stats[0][tid], t);
    }
    __syncthreads();
#pragma unroll
    for (int j = 0; j < 8; j++) red[tm][tn * 8 + j] = s2[j];
    __syncthreads();
    if (tid < HH) {
        float t = 0.f;
#pragma unroll
        for (int w = 0; w < 16; w++) t += red[w][tid];
        atomicAdd(&g_stats[0][HH + tid], t);
    }
}

// ---------------- FP16 mma.sync dual GEMM (fragment-order smem layouts) ----------------
#define BF_UINTS (2 * 8 * 8 * 128)
#define AF_UINTS (8 * 8 * 132)
#define OFF_BF   0
#define OFF_AF   (BF_UINTS * 4)
#define OFF_NSC  (OFF_AF + AF_UINTS * 4)
#define OFF_NSH  (OFF_NSC + 512)
#define MMA_SMEM (OFF_NSH + 512)

__global__ __launch_bounds__(256, 1) void k_gemm_mma(
    const float* __restrict__ Wl, const float* __restrict__ Wr,
    const float* __restrict__ gw, const float* __restrict__ gb,
    const float* __restrict__ ga, int Lm1)
{
    extern __shared__ char sm[];
    uint*  Bf  = (uint*)(sm + OFF_BF);
    uint*  Af  = (uint*)(sm + OFF_AF);
    float* nsc = (float*)(sm + OFF_NSC);
    float* nsh = (float*)(sm + OFF_NSH);
    int tid = threadIdx.x;
    int wid = tid >> 5, lane = tid & 31;
    int tq = lane >> 2, tr = lane & 3;
    int rg = wid & 3, cg = wid >> 2;

    if (tid < HH) {
        float invn = 1.f / (float)NN;
        float m  = g_stats[Lm1][tid] * invn;
        float e2 = g_stats[Lm1][HH + tid] * invn;
        float a = ga[tid];
        float var = fmaxf(e2 - m * m * (2.f * a - a * a), 0.f);
        float scale = gw[tid] * rsqrtf(var + EPSV);
        nsc[tid] = scale;
        nsh[tid] = gb[tid] - a * m * scale;
    }

    for (int e = tid; e < 256 * 32; e += 256) {
        int c = e >> 5, c4 = e & 31;
        const float4* src = (const float4*)((c < 128) ? Wl : Wr);
        float4 v = src[(c & 127) * 32 + c4];
        uint h0 = pack_h2(v.x, v.y);
        uint h1 = pack_h2(v.z, v.w);
        int cgi = c >> 7, cl = c & 127;
        int j = cl >> 3, jp = j >> 1, jl = j & 1, nq = cl & 7;
        int p = 2 * c4;
        int k16 = p >> 3, q = p & 7;
        int reg = (q >= 4) ? 1 : 0;
        uint* dst = Bf + (((cgi * 8 + k16) * 8 + jp) << 7) + jl * 2 + reg;
        dst[(nq * 4 + (q & 3)) * 4]       = h0;
        dst[(nq * 4 + ((q + 1) & 3)) * 4] = h1;
    }

    const float4* P4 = (const float4*)g_pre;

    for (int tile = blockIdx.x; tile < NTILES; tile += gridDim.x) {
        int m0 = tile * 128;
        __syncthreads();
        for (int e = tid; e < 128 * 32; e += 256) {
            int r = e >> 5, c4 = e & 31;
            int row = m0 + r;
            float4 v = make_float4(0.f, 0.f, 0.f, 0.f);
            if (row < NN) v = P4[row * 32 + c4];
            int c = c4 * 4;
            float g0 = gelu_f(v.x * nsc[c + 0] + nsh[c + 0]);
            float g1 = gelu_f(v.y * nsc[c + 1] + nsh[c + 1]);
            float g2 = gelu_f(v.z * nsc[c + 2] + nsh[c + 2]);
            float g3 = gelu_f(v.w * nsc[c + 3] + nsh[c + 3]);
            uint h0 = pack_h2(g0, g1);
            uint h1 = pack_h2(g2, g3);
            int rt = r >> 4, rr = r & 15, rh = rr >> 3, tq_ = rr & 7;
            int p = 2 * c4;
            int k16 = p >> 3, q = p & 7;
            int reg = ((q >= 4) ? 2 : 0) + rh;
            uint* dst = Af + (rt * 8 + k16) * 132 + reg;
            dst[(tq_ * 4 + (q & 3)) * 4]       = h0;
            dst[(tq_ * 4 + ((q + 1) & 3)) * 4] = h1;
        }
        __syncthreads();

        int rt0 = rg * 2, rt1 = rg * 2 + 1;
        float acc[2][16][4];
#pragma unroll
        for (int t2 = 0; t2 < 2; t2++)
#pragma unroll
            for (int j = 0; j < 16; j++)
#pragma unroll
                for (int c = 0; c < 4; c++) acc[t2][j][c] = 0.f;

#pragma unroll
        for (int k16 = 0; k16 < 8; k16++) {
            uint4 A0 = ((const uint4*)(Af + (rt0 * 8 + k16) * 132))[lane];
            uint4 A1 = ((const uint4*)(Af + (rt1 * 8 + k16) * 132))[lane];
            const uint4* Bp = (const uint4*)(Bf + (((cg * 8 + k16) * 8) << 7));
#pragma unroll
            for (int jp = 0; jp < 8; jp++) {
                uint4 B = Bp[(jp << 5) + lane];
                mma_f16(acc[0][jp * 2],     A0.x, A0.y, A0.z, A0.w, B.x, B.y);
                mma_f16(acc[1][jp * 2],     A1.x, A1.y, A1.z, A1.w, B.x, B.y);
                mma_f16(acc[0][jp * 2 + 1], A0.x, A0.y, A0.z, A0.w, B.z, B.w);
                mma_f16(acc[1][jp * 2 + 1], A1.x, A1.y, A1.z, A1.w, B.z, B.w);
            }
        }

#pragma unroll
        for (int t2 = 0; t2 < 2; t2++) {
            int row0 = m0 + rg * 32 + t2 * 16 + tq;
            if (cg == 0) {
#pragma unroll
                for (int j = 0; j < 16; j++) {
                    int hidx = j * 4 + tr;
                    if (row0 < NN)
                        g_yl16[row0 * 64 + hidx] = pack_h2(acc[t2][j][0], acc[t2][j][1]);
                    if (row0 + 8 < NN)
                        g_yl16[(row0 + 8) * 64 + hidx] = pack_h2(acc[t2][j][2], acc[t2][j][3]);
                }
            } else {
#pragma unroll
                for (int j = 0; j < 16; j++) {
                    int col = j * 8 + tr * 2;
                    if (row0 < NN)
                        *(float2*)(g_yr + row0 * HH + col) = make_float2(acc[t2][j][0], acc[t2][j][1]);
                    if (row0 + 8 < NN)
                        *(float2*)(g_yr + (row0 + 8) * HH + col) = make_float2(acc[t2][j][2], acc[t2][j][3]);
                }
            }
        }
    }
}

// ---------------- aggregation of yl(fp16) + add yr + bias + stats (unroll 4) ----------------
__global__ __launch_bounds__(256) void k_aggstats(const float* __restrict__ bl, int L)
{
    __shared__ float red[8][HH];
    int tid = threadIdx.x;
    int lane = tid & 31, wp = tid >> 5;
    const uint2* yl2 = (const uint2*)g_yl16;
    const float4* yr4 = (const float4*)g_yr;
    float4 bias = ((const float4*)bl)[lane];
    float s[4] = {0, 0, 0, 0}, s2[4] = {0, 0, 0, 0};
    int gw = blockIdx.x * 8 + wp;
    const int stride = gridDim.x * 8;
    for (int w = gw; w < NN; w += stride) {
        int off = g_off[w], end = g_off[w + 1];
        float4 acc = make_float4(0.f, 0.f, 0.f, 0.f);
        for (int j = off; j < end; j += 32) {
            int idx = (j + lane < end) ? g_csr[j + lane] : 0;
            int cnt = min(32, end - j);
            int t = 0;
            for (; t + 4 <= cnt; t += 4) {
                int s0 = __shfl_sync(0xffffffffu, idx, t);
                int s1 = __shfl_sync(0xffffffffu, idx, t + 1);
                int s2i = __shfl_sync(0xffffffffu, idx, t + 2);
                int s3 = __shfl_sync(0xffffffffu, idx, t + 3);
                uint2 u0 = yl2[s0 * 32 + lane];
                uint2 u1 = yl2[s1 * 32 + lane];
                uint2 u2 = yl2[s2i * 32 + lane];
                uint2 u3 = yl2[s3 * 32 + lane];
                float2 a0 = __half22float2(*(const __half2*)&u0.x);
                float2 b0 = __half22float2(*(const __half2*)&u0.y);
                float2 a1 = __half22float2(*(const __half2*)&u1.x);
                float2 b1 = __half22float2(*(const __half2*)&u1.y);
                float2 a2 = __half22float2(*(const __half2*)&u2.x);
                float2 b2 = __half22float2(*(const __half2*)&u2.y);
                float2 a3 = __half22float2(*(const __half2*)&u3.x);
                float2 b3 = __half22float2(*(const __half2*)&u3.y);
                acc.x += (a0.x + a1.x) + (a2.x + a3.x);
                acc.y += (a0.y + a1.y) + (a2.y + a3.y);
                acc.z += (b0.x + b1.x) + (b2.x + b3.x);
                acc.w += (b0.y + b1.y) + (b2.y + b3.y);
            }
            for (; t < cnt; t++) {
                int sx = __shfl_sync(0xffffffffu, idx, t);
                uint2 u = yl2[sx * 32 + lane];
                float2 a = __half22float2(*(const __half2*)&u.x);
                float2 b = __half22float2(*(const __half2*)&u.y);
                acc.x += a.x; acc.y += a.y; acc.z += b.x; acc.w += b.y;
            }
        }
        int deg = end - off;
        float inv = (deg > 0) ? 1.f / (float)deg : 0.f;
        float4 r = yr4[w * 32 + lane];
        r.x = acc.x * inv + r.x + bias.x;
        r.y = acc.y * inv + r.y + bias.y;
        r.z = acc.z * inv + r.z + bias.z;
        r.w = acc.w * inv + r.w + bias.w;
        ((float4*)g_pre)[w * 32 + lane] = r;
        s[0] += r.x; s2[0] += r.x * r.x;
        s[1] += r.y; s2[1] += r.y * r.y;
        s[2] += r.z; s2[2] += r.z * r.z;
        s[3] += r.w; s2[3] += r.w * r.w;
    }
#pragma unroll
    for (int i = 0; i < 4; i++) red[wp][lane * 4 + i] = s[i];
    __syncthreads();
    if (tid < HH) {
        float t = 0.f;
#pragma unroll
        for (int w = 0; w < 8; w++) t += red[w][tid];
        atomicAdd(&g_stats[L][tid], t);
    }
    __syncthreads();
#pragma unroll
    for (int i = 0; i < 4; i++) red[wp][lane * 4 + i] = s2[i];
    __syncthreads();
    if (tid < HH) {
        float t = 0.f;
#pragma unroll
        for (int w = 0; w < 8; w++) t += red[w][tid];
        atomicAdd(&g_stats[L][HH + tid], t);
    }
}

// ---------------- fused MLP head: 256 threads, 2 node-tiles/block ----------------
#define MLP_W   (8192 + 2048 + 32 + 64 + 32 + 256)     // weights+consts floats
#define MLP_SMEM ((MLP_W + 2 * 128 * 129) * 4)

__global__ __launch_bounds__(256) void k_mlp(
    const float* __restrict__ hW1, const float* __restrict__ hb1,
    const float* __restrict__ hW2, const float* __restrict__ hb2,
    const float* __restrict__ hW3, const float* __restrict__ hb3,
    const float* __restrict__ gw2, const float* __restrict__ gb2,
    const float* __restrict__ ga2,
    float* __restrict__ out)
{
    extern __shared__ float smf[];
    float* W1t = smf;                // [128][64]
    float* W2t = W1t + 128 * 64;     // [64][32]
    float* w3  = W2t + 64 * 32;      // [32]
    float* b1  = w3 + 32;            // [64]
    float* b2  = b1 + 64;            // [32]
    float* nsc = b2 + 32;            // [128]
    float* nsh = nsc + 128;          // [128]
    float* hs0 = nsh + 128;          // [2][128][129]

    int tid = threadIdx.x;
    int half = tid >> 7, lt = tid & 127;
    for (int e = tid; e < 8192; e += 256) { int o = e >> 7, k = e & 127; W1t[k * 64 + o] = hW1[e]; }
    for (int e = tid; e < 2048; e += 256) { int o = e >> 6, k = e & 63;  W2t[k * 32 + o] = hW2[e]; }
    if (tid < 32) w3[tid] = hW3[tid];
    if (tid < 64) b1[tid] = hb1[tid];
    if (tid >= 64 && tid < 96) b2[tid - 64] = hb2[tid - 64];
    if (tid < 128) {
        float invn = 1.f / (float)NN;
        float m  = g_stats[2][tid] * invn;
        float e2 = g_stats[2][HH + tid] * invn;
        float a = ga2[tid];
        float var = fmaxf(e2 - m * m * (2.f * a - a * a), 0.f);
        float scale = gw2[tid] * rsqrtf(var + EPSV);
        nsc[tid] = scale;
        nsh[tid] = gb2[tid] - a * m * scale;
    }
    __syncthreads();

    float* hs = hs0 + half * (128 * 129);
    int n0 = blockIdx.x * 256 + half * 128;
    const float4* p4 = (const float4*)g_pre;
    for (int e = lt; e < 128 * 32; e += 128) {
        int r = e >> 5, cc = e & 31;
        int n = n0 + r;
        float4 v = make_float4(0.f, 0.f, 0.f, 0.f);
        if (n < NN) v = p4[n * 32 + cc];
        int c = cc * 4;
        hs[(c + 0) * 129 + r] = gelu_f(v.x * nsc[c + 0] + nsh[c + 0]);
        hs[(c + 1) * 129 + r] = gelu_f(v.y * nsc[c + 1] + nsh[c + 1]);
        hs[(c + 2) * 129 + r] = gelu_f(v.z * nsc[c + 2] + nsh[c + 2]);
        hs[(c + 3) * 129 + r] = gelu_f(v.w * nsc[c + 3] + nsh[c + 3]);
    }
    __syncthreads();

    int n = n0 + lt;
    if (n >= NN) return;

    ull acc1[32];
#pragma unroll
    for (int i = 0; i < 32; i++) acc1[i] = pk2(b1[2 * i], b1[2 * i + 1]);
    for (int k = 0; k < 128; k++) {
        float hv = hs[k * 129 + lt];
        ull a2 = pk2(hv, hv);
        const ull* wr = (const ull*)(W1t + k * 64);
#pragma unroll
        for (int i = 0; i < 32; i++) fma2(acc1[i], a2, wr[i]);
    }
    float y1[64];
#pragma unroll
    for (int i = 0; i < 32; i++) {
        float lo, hi;
        upk2(acc1[i], lo, hi);
        y1[2 * i] = gelu_f(lo);
        y1[2 * i + 1] = gelu_f(hi);
    }
    ull acc2[16];
#pragma unroll
    for (int i = 0; i < 16; i++) acc2[i] = pk2(b2[2 * i], b2[2 * i + 1]);
#pragma unroll 4
    for (int k = 0; k < 64; k++) {
        ull a2 = pk2(y1[k], y1[k]);
        const ull* wr = (const ull*)(W2t + k * 32);
#pragma unroll
        for (int i = 0; i < 16; i++) fma2(acc2[i], a2, wr[i]);
    }
    float s = 0.f;
#pragma unroll
    for (int i = 0; i < 16; i++) {
        float lo, hi;
        upk2(acc2[i], lo, hi);
        s += gelu_f(lo) * w3[2 * i] + gelu_f(hi) * w3[2 * i + 1];
    }
    s += hb3[0];
    out[n] = 1.f / (1.f + expf(-s));
}

// ---------------- launch ----------------
extern "C" void kernel_launch(void* const* d_in, const int* in_sizes, int n_in,
                              void* d_out, int out_size)
{
    const float* x   = (const float*)d_in[0];
    const int*   ei  = (const int*)d_in[1];
    const float* Wl[3] = {(const float*)d_in[2],  (const float*)d_in[8],  (const float*)d_in[14]};
    const float* bl[3] = {(const float*)d_in[3],  (const float*)d_in[9],  (const float*)d_in[15]};
    const float* Wr[3] = {(const float*)d_in[4],  (const float*)d_in[10], (const float*)d_in[16]};
    const float* gw[3] = {(const float*)d_in[5],  (const float*)d_in[11], (const float*)d_in[17]};
    const float* gb[3] = {(const float*)d_in[6],  (const float*)d_in[12], (const float*)d_in[18]};
    const float* ga[3] = {(const float*)d_in[7],  (const float*)d_in[13], (const float*)d_in[19]};
    const float* hW1 = (const float*)d_in[20];
    const float* hb1 = (const float*)d_in[21];
    const float* hW2 = (const float*)d_in[22];
    const float* hb2 = (const float*)d_in[23];
    const float* hW3 = (const float*)d_in[24];
    const float* hb3 = (const float*)d_in[25];
    float* out = (float*)d_out;

    const int SCAN_BLOCKS = (NN + 1023) / 1024;      // 98
    cudaFuncSetAttribute(k_mlp, cudaFuncAttributeMaxDynamicSharedMemorySize, MLP_SMEM);
    cudaFuncSetAttribute(k_gemm_mma, cudaFuncAttributeMaxDynamicSharedMemorySize, MMA_SMEM);

    // CSR build (merged scan, shfl scan1)
    k_init<<<(NN + 255) / 256, 256>>>();
    k_hist<<<(EE + 255) / 256, 256>>>(ei);
    k_scan1<<<SCAN_BLOCKS, 1024>>>();
    k_scan3<<<(NN + 255) / 256, 256>>>(SCAN_BLOCKS);
    k_fill<<<(EE + 255) / 256, 256>>>(ei);

    // layer 0
    k_agg20<<<(NN * 32 + 255) / 256, 256>>>(x);
    k_gemm0<<<(NN + 63) / 64, 256>>>(x, Wl[0], bl[0], Wr[0]);

    // layers 1, 2
    for (int L = 1; L <= 2; L++) {
        k_gemm_mma<<<148, 256, MMA_SMEM>>>(Wl[L], Wr[L], gw[L - 1], gb[L - 1], ga[L - 1], L - 1);
        k_aggstats<<<1564, 256>>>(bl[L], L);
    }

    // MLP head (2 tiles/block)
    k_mlp<<<(NN + 255) / 256, 256, MLP_SMEM>>>(hW1, hb1, hW2, hb2, hW3, hb3,
                                               gw[2], gb[2], ga[2], out);
}

// round 13
// speedup vs baseline: 1.0229x; 1.0229x over previous
#include <cuda_runtime.h>
#include <cuda_fp16.h>
#include <math.h>

#define NN   100000
#define EE   1600000
#define FIN  20
#define HH   128
#define EPSV 1e-5f
#define NTILES 782            // ceil(NN/128)

// ---------------- scratch ----------------
__device__ __align__(16) unsigned int g_yl8[NN * 32];    // fp8 e4m3 x4: [N][32] uint = 128 ch
__device__ __align__(16) float g_yr[NN * HH];
__device__ __align__(16) float g_pre[NN * HH];
__device__ __align__(16) float g_a20[NN * FIN];
__device__ int   g_deg[NN];
__device__ int   g_off[NN + 1];
__device__ int   g_csr[EE];
__device__ int   g_bsum[128];
__device__ float g_stats[3][2 * HH];

typedef unsigned long long ull;
typedef unsigned int uint;
typedef unsigned short ushort;

__device__ __forceinline__ ull pk2(float lo, float hi) {
    ull r; asm("mov.b64 %0, {%1,%2};" : "=l"(r) : "f"(lo), "f"(hi)); return r;
}
__device__ __forceinline__ void upk2(ull v, float& lo, float& hi) {
    asm("mov.b64 {%0,%1}, %2;" : "=f"(lo), "=f"(hi) : "l"(v));
}
__device__ __forceinline__ void fma2(ull& d, ull a, ull b) {
    asm("fma.rn.f32x2 %0, %1, %2, %0;" : "+l"(d) : "l"(a), "l"(b));
}
__device__ __forceinline__ float gelu_f(float x) {
    return 0.5f * x * (1.0f + erff(x * 0.70710678118654752f));
}
__device__ __forceinline__ uint pack_h2(float lo, float hi) {
    uint r; asm("cvt.rn.f16x2.f32 %0, %2, %1;" : "=r"(r) : "f"(lo), "f"(hi)); return r;
}
__device__ __forceinline__ ushort pack_e4(float lo, float hi) {
    ushort r; asm("cvt.rn.satfinite.e4m3x2.f32 %0, %2, %1;" : "=h"(r) : "f"(lo), "f"(hi));
    return r;
}
__device__ __forceinline__ float2 e4_to_f2(ushort v) {
    uint h; asm("cvt.rn.f16x2.e4m3x2 %0, %1;" : "=r"(h) : "h"(v));
    return __half22float2(*(__half2*)&h);
}
__device__ __forceinline__ void acc_e4(float4& a, uint u) {
    float2 lo = e4_to_f2((ushort)(u & 0xffffu));
    float2 hi = e4_to_f2((ushort)(u >> 16));
    a.x += lo.x; a.y += lo.y; a.z += hi.x; a.w += hi.y;
}
__device__ __forceinline__ void mma_f16(float* d, uint a0, uint a1, uint a2, uint a3,
                                        uint b0, uint b1) {
    asm volatile(
        "mma.sync.aligned.m16n8k16.row.col.f32.f16.f16.f32 "
        "{%0,%1,%2,%3}, {%4,%5,%6,%7}, {%8,%9}, {%0,%1,%2,%3};"
        : "+f"(d[0]), "+f"(d[1]), "+f"(d[2]), "+f"(d[3])
        : "r"(a0), "r"(a1), "r"(a2), "r"(a3), "r"(b0), "r"(b1));
}

// ---------------- init + CSR build ----------------
__global__ void k_init() {
    int i = blockIdx.x * blockDim.x + threadIdx.x;
    if (i < NN) g_deg[i] = 0;
    if (i < 3 * 2 * HH) ((float*)g_stats)[i] = 0.f;
}
__global__ void k_hist(const int* __restrict__ ei) {
    int e = blockIdx.x * blockDim.x + threadIdx.x;
    if (e < EE) atomicAdd(&g_deg[ei[EE + e]], 1);
}
__global__ void k_scan1() {
    __shared__ int s[1024];
    int t = threadIdx.x;
    int i = blockIdx.x * 1024 + t;
    int v = (i < NN) ? g_deg[i] : 0;
    s[t] = v;
    __syncthreads();
#pragma unroll
    for (int d = 1; d < 1024; d <<= 1) {
        int x = (t >= d) ? s[t - d] : 0;
        __syncthreads();
        s[t] += x;
        __syncthreads();
    }
    if (i < NN) g_off[i + 1] = s[t];
    if (t == 1023) g_bsum[blockIdx.x] = s[1023];
}
// merged scan2+scan3 (verified): all 256 threads reach every barrier.
__global__ void k_scan3(int nb) {
    __shared__ int ex[128];
    int t = threadIdx.x;
    int run = 0;
    if (t < 128) {
        run = (t < nb) ? g_bsum[t] : 0;
        ex[t] = run;
    }
    __syncthreads();
#pragma unroll
    for (int d = 1; d < 128; d <<= 1) {
        int x = 0;
        if (t < 128 && t >= d) x = ex[t - d];
        __syncthreads();
        if (t < 128) ex[t] += x;
        __syncthreads();
    }
    if (t < 128) ex[t] -= run;   // exclusive
    __syncthreads();
    int i = blockIdx.x * blockDim.x + t;
    if (i < NN) {
        int tot = g_off[i + 1] + ex[i >> 10];
        g_off[i + 1] = tot;
        int d = g_deg[i];
        g_deg[i] = tot - d;
        if (i == 0) g_off[0] = 0;
    }
}
__global__ void k_fill(const int* __restrict__ ei) {
    int e = blockIdx.x * blockDim.x + threadIdx.x;
    if (e < EE) {
        int d = ei[EE + e];
        int pos = atomicAdd(&g_deg[d], 1);
        g_csr[pos] = ei[e];
    }
}

// ---------------- layer-0 aggregation (20 cols, 1 warp/node) ----------------
__global__ void k_agg20(const float* __restrict__ x) {
    int w = (blockIdx.x * blockDim.x + threadIdx.x) >> 5;
    int lane = threadIdx.x & 31;
    if (w >= NN) return;
    int off = g_off[w], end = g_off[w + 1];
    float acc = 0.f;
    for (int j = off; j < end; j += 32) {
        int idx = (j + lane < end) ? g_csr[j + lane] : 0;
        int cnt = min(32, end - j);
        int t = 0;
        for (; t + 4 <= cnt; t += 4) {
            int s0 = __shfl_sync(0xffffffffu, idx, t);
            int s1 = __shfl_sync(0xffffffffu, idx, t + 1);
            int s2 = __shfl_sync(0xffffffffu, idx, t + 2);
            int s3 = __shfl_sync(0xffffffffu, idx, t + 3);
            if (lane < FIN) {
                float v0 = x[s0 * FIN + lane], v1 = x[s1 * FIN + lane];
                float v2 = x[s2 * FIN + lane], v3 = x[s3 * FIN + lane];
                acc += (v0 + v1) + (v2 + v3);
            }
        }
        for (; t < cnt; t++) {
            int s = __shfl_sync(0xffffffffu, idx, t);
            if (lane < FIN) acc += x[s * FIN + lane];
        }
    }
    if (lane < FIN) {
        int deg = end - off;
        g_a20[w * FIN + lane] = acc * (deg > 0 ? 1.f / (float)deg : 0.f);
    }
}

// ---------------- layer-0 GEMM (K=20) + bias + stats ----------------
__global__ __launch_bounds__(256) void k_gemm0(
    const float* __restrict__ x, const float* __restrict__ Wl,
    const float* __restrict__ bl, const float* __restrict__ Wr)
{
    __shared__ float Wls[FIN][HH], Wrs[FIN][HH], bls[HH];
    __shared__ float As[64][FIN + 1], Xs[64][FIN + 1];
    __shared__ float red[16][HH];
    int tid = threadIdx.x;
    for (int e = tid; e < HH * FIN; e += 256) {
        int o = e / FIN, k = e % FIN;
        Wls[k][o] = Wl[e];
        Wrs[k][o] = Wr[e];
    }
    if (tid < HH) bls[tid] = bl[tid];
    int n0 = blockIdx.x * 64;
    for (int e = tid; e < 64 * FIN; e += 256) {
        int i = e / FIN, k = e % FIN;
        int n = n0 + i;
        As[i][k] = (n < NN) ? g_a20[n * FIN + k] : 0.f;
        Xs[i][k] = (n < NN) ? x[n * FIN + k] : 0.f;
    }
    __syncthreads();
    int tm = tid >> 4, tn = tid & 15;
    ull acc[4][4];
#pragma unroll
    for (int r = 0; r < 4; r++)
#pragma unroll
        for (int c = 0; c < 4; c++)
            acc[r][c] = pk2(bls[tn * 8 + 2 * c], bls[tn * 8 + 2 * c + 1]);
#pragma unroll 4
    for (int k = 0; k < FIN; k++) {
        const ull* wl = (const ull*)&Wls[k][tn * 8];
        const ull* wr = (const ull*)&Wrs[k][tn * 8];
#pragma unroll
        for (int r = 0; r < 4; r++) {
            ull a2 = pk2(As[tm * 4 + r][k], As[tm * 4 + r][k]);
            ull x2 = pk2(Xs[tm * 4 + r][k], Xs[tm * 4 + r][k]);
#pragma unroll
            for (int c = 0; c < 4; c++) { fma2(acc[r][c], a2, wl[c]); fma2(acc[r][c], x2, wr[c]); }
        }
    }
    float av[4][8];
    float s[8] = {0,0,0,0,0,0,0,0}, s2[8] = {0,0,0,0,0,0,0,0};
#pragma unroll
    for (int r = 0; r < 4; r++) {
#pragma unroll
        for (int c = 0; c < 4; c++) upk2(acc[r][c], av[r][2 * c], av[r][2 * c + 1]);
        int n = n0 + tm * 4 + r;
        if (n < NN) {
            float4* o4 = (float4*)(g_pre + n * HH + tn * 8);
            o4[0] = make_float4(av[r][0], av[r][1], av[r][2], av[r][3]);
            o4[1] = make_float4(av[r][4], av[r][5], av[r][6], av[r][7]);
#pragma unroll
            for (int j = 0; j < 8; j++) { s[j] += av[r][j]; s2[j] += av[r][j] * av[r][j]; }
        }
    }
#pragma unroll
    for (int j = 0; j < 8; j++) red[tm][tn * 8 + j] = s[j];
    __syncthreads();
    if (tid < HH) {
        float t = 0.f;
#pragma unroll
        for (int w = 0; w < 16; w++) t += red[w][tid];
        atomicAdd(&g_stats[0][tid], t);
    }
    __syncthreads();
#pragma unroll
    for (int j = 0; j < 8; j++) red[tm][tn * 8 + j] = s2[j];
    __syncthreads();
    if (tid < HH) {
        float t = 0.f;
#pragma unroll
        for (int w = 0; w < 16; w++) t += red[w][tid];
        atomicAdd(&g_stats[0][HH + tid], t);
    }
}

// ---------------- FP16 mma.sync dual GEMM (fragment-order smem layouts) ----------------
#define BF_UINTS (2 * 8 * 8 * 128)
#define AF_UINTS (8 * 8 * 132)
#define OFF_BF   0
#define OFF_AF   (BF_UINTS * 4)
#define OFF_NSC  (OFF_AF + AF_UINTS * 4)
#define OFF_NSH  (OFF_NSC + 512)
#define MMA_SMEM (OFF_NSH + 512)

__global__ __launch_bounds__(256, 1) void k_gemm_mma(
    const float* __restrict__ Wl, const float* __restrict__ Wr,
    const float* __restrict__ gw, const float* __restrict__ gb,
    const float* __restrict__ ga, int Lm1)
{
    extern __shared__ char sm[];
    uint*  Bf  = (uint*)(sm + OFF_BF);
    uint*  Af  = (uint*)(sm + OFF_AF);
    float* nsc = (float*)(sm + OFF_NSC);
    float* nsh = (float*)(sm + OFF_NSH);
    int tid = threadIdx.x;
    int wid = tid >> 5, lane = tid & 31;
    int tq = lane >> 2, tr = lane & 3;
    int rg = wid & 3, cg = wid >> 2;

    if (tid < HH) {
        float invn = 1.f / (float)NN;
        float m  = g_stats[Lm1][tid] * invn;
        float e2 = g_stats[Lm1][HH + tid] * invn;
        float a = ga[tid];
        float var = fmaxf(e2 - m * m * (2.f * a - a * a), 0.f);
        float scale = gw[tid] * rsqrtf(var + EPSV);
        nsc[tid] = scale;
        nsh[tid] = gb[tid] - a * m * scale;
    }

    for (int e = tid; e < 256 * 32; e += 256) {
        int c = e >> 5, c4 = e & 31;
        const float4* src = (const float4*)((c < 128) ? Wl : Wr);
        float4 v = src[(c & 127) * 32 + c4];
        uint h0 = pack_h2(v.x, v.y);
        uint h1 = pack_h2(v.z, v.w);
        int cgi = c >> 7, cl = c & 127;
        int j = cl >> 3, jp = j >> 1, jl = j & 1, nq = cl & 7;
        int p = 2 * c4;
        int k16 = p >> 3, q = p & 7;
        int reg = (q >= 4) ? 1 : 0;
        uint* dst = Bf + (((cgi * 8 + k16) * 8 + jp) << 7) + jl * 2 + reg;
        dst[(nq * 4 + (q & 3)) * 4]       = h0;
        dst[(nq * 4 + ((q + 1) & 3)) * 4] = h1;
    }

    const float4* P4 = (const float4*)g_pre;

    for (int tile = blockIdx.x; tile < NTILES; tile += gridDim.x) {
        int m0 = tile * 128;
        __syncthreads();
        for (int e = tid; e < 128 * 32; e += 256) {
            int r = e >> 5, c4 = e & 31;
            int row = m0 + r;
            float4 v = make_float4(0.f, 0.f, 0.f, 0.f);
            if (row < NN) v = P4[row * 32 + c4];
            int c = c4 * 4;
            float g0 = gelu_f(v.x * nsc[c + 0] + nsh[c + 0]);
            float g1 = gelu_f(v.y * nsc[c + 1] + nsh[c + 1]);
            float g2 = gelu_f(v.z * nsc[c + 2] + nsh[c + 2]);
            float g3 = gelu_f(v.w * nsc[c + 3] + nsh[c + 3]);
            uint h0 = pack_h2(g0, g1);
            uint h1 = pack_h2(g2, g3);
            int rt = r >> 4, rr = r & 15, rh = rr >> 3, tq_ = rr & 7;
            int p = 2 * c4;
            int k16 = p >> 3, q = p & 7;
            int reg = ((q >= 4) ? 2 : 0) + rh;
            uint* dst = Af + (rt * 8 + k16) * 132 + reg;
            dst[(tq_ * 4 + (q & 3)) * 4]       = h0;
            dst[(tq_ * 4 + ((q + 1) & 3)) * 4] = h1;
        }
        __syncthreads();

        int rt0 = rg * 2, rt1 = rg * 2 + 1;
        float acc[2][16][4];
#pragma unroll
        for (int t2 = 0; t2 < 2; t2++)
#pragma unroll
            for (int j = 0; j < 16; j++)
#pragma unroll
                for (int c = 0; c < 4; c++) acc[t2][j][c] = 0.f;

#pragma unroll
        for (int k16 = 0; k16 < 8; k16++) {
            uint4 A0 = ((const uint4*)(Af + (rt0 * 8 + k16) * 132))[lane];
            uint4 A1 = ((const uint4*)(Af + (rt1 * 8 + k16) * 132))[lane];
            const uint4* Bp = (const uint4*)(Bf + (((cg * 8 + k16) * 8) << 7));
#pragma unroll
            for (int jp = 0; jp < 8; jp++) {
                uint4 B = Bp[(jp << 5) + lane];
                mma_f16(acc[0][jp * 2],     A0.x, A0.y, A0.z, A0.w, B.x, B.y);
                mma_f16(acc[1][jp * 2],     A1.x, A1.y, A1.z, A1.w, B.x, B.y);
                mma_f16(acc[0][jp * 2 + 1], A0.x, A0.y, A0.z, A0.w, B.z, B.w);
                mma_f16(acc[1][jp * 2 + 1], A1.x, A1.y, A1.z, A1.w, B.z, B.w);
            }
        }

#pragma unroll
        for (int t2 = 0; t2 < 2; t2++) {
            int row0 = m0 + rg * 32 + t2 * 16 + tq;
            if (cg == 0) {
                ushort* yl8s = (ushort*)g_yl8;
#pragma unroll
                for (int j = 0; j < 16; j++) {
                    int hidx = j * 4 + tr;     // ushort index (cols j*8+tr*2, +1)
                    if (row0 < NN)
                        yl8s[row0 * 64 + hidx] = pack_e4(acc[t2][j][0], acc[t2][j][1]);
                    if (row0 + 8 < NN)
                        yl8s[(row0 + 8) * 64 + hidx] = pack_e4(acc[t2][j][2], acc[t2][j][3]);
                }
            } else {
#pragma unroll
                for (int j = 0; j < 16; j++) {
                    int col = j * 8 + tr * 2;
                    if (row0 < NN)
                        *(float2*)(g_yr + row0 * HH + col) = make_float2(acc[t2][j][0], acc[t2][j][1]);
                    if (row0 + 8 < NN)
                        *(float2*)(g_yr + (row0 + 8) * HH + col) = make_float2(acc[t2][j][2], acc[t2][j][3]);
                }
            }
        }
    }
}

// ---------------- aggregation of yl(fp8) + add yr + bias + stats (unroll 4) ----------------
__global__ __launch_bounds__(256) void k_aggstats(const float* __restrict__ bl, int L)
{
    __shared__ float red[8][HH];
    int tid = threadIdx.x;
    int lane = tid & 31, wp = tid >> 5;
    const uint* yl1 = (const uint*)g_yl8;       // lane covers ch lane*4..+3 (1 uint)
    const float4* yr4 = (const float4*)g_yr;
    float4 bias = ((const float4*)bl)[lane];
    float s[4] = {0, 0, 0, 0}, s2[4] = {0, 0, 0, 0};
    int gw = blockIdx.x * 8 + wp;
    const int stride = gridDim.x * 8;
    for (int w = gw; w < NN; w += stride) {
        int off = g_off[w], end = g_off[w + 1];
        float4 acc = make_float4(0.f, 0.f, 0.f, 0.f);
        for (int j = off; j < end; j += 32) {
            int idx = (j + lane < end) ? g_csr[j + lane] : 0;
            int cnt = min(32, end - j);
            int t = 0;
            for (; t + 4 <= cnt; t += 4) {
                int s0 = __shfl_sync(0xffffffffu, idx, t);
                int s1 = __shfl_sync(0xffffffffu, idx, t + 1);
                int s2i = __shfl_sync(0xffffffffu, idx, t + 2);
                int s3 = __shfl_sync(0xffffffffu, idx, t + 3);
                uint u0 = yl1[s0 * 32 + lane];
                uint u1 = yl1[s1 * 32 + lane];
                uint u2 = yl1[s2i * 32 + lane];
                uint u3 = yl1[s3 * 32 + lane];
                acc_e4(acc, u0); acc_e4(acc, u1); acc_e4(acc, u2); acc_e4(acc, u3);
            }
            for (; t < cnt; t++) {
                int sx = __shfl_sync(0xffffffffu, idx, t);
                acc_e4(acc, yl1[sx * 32 + lane]);
            }
        }
        int deg = end - off;
        float inv = (deg > 0) ? 1.f / (float)deg : 0.f;
        float4 r = yr4[w * 32 + lane];
        r.x = acc.x * inv + r.x + bias.x;
        r.y = acc.y * inv + r.y + bias.y;
        r.z = acc.z * inv + r.z + bias.z;
        r.w = acc.w * inv + r.w + bias.w;
        ((float4*)g_pre)[w * 32 + lane] = r;
        s[0] += r.x; s2[0] += r.x * r.x;
        s[1] += r.y; s2[1] += r.y * r.y;
        s[2] += r.z; s2[2] += r.z * r.z;
        s[3] += r.w; s2[3] += r.w * r.w;
    }
#pragma unroll
    for (int i = 0; i < 4; i++) red[wp][lane * 4 + i] = s[i];
    __syncthreads();
    if (tid < HH) {
        float t = 0.f;
#pragma unroll
        for (int w = 0; w < 8; w++) t += red[w][tid];
        atomicAdd(&g_stats[L][tid], t);
    }
    __syncthreads();
#pragma unroll
    for (int i = 0; i < 4; i++) red[wp][lane * 4 + i] = s2[i];
    __syncthreads();
    if (tid < HH) {
        float t = 0.f;
#pragma unroll
        for (int w = 0; w < 8; w++) t += red[w][tid];
        atomicAdd(&g_stats[L][HH + tid], t);
    }
}

// ---------------- fused MLP head: 256 threads, 2 node-tiles/block ----------------
#define MLP_W   (8192 + 2048 + 32 + 64 + 32 + 256)     // weights+consts floats
#define MLP_SMEM ((MLP_W + 2 * 128 * 129) * 4)

__global__ __launch_bounds__(256) void k_mlp(
    const float* __restrict__ hW1, const float* __restrict__ hb1,
    const float* __restrict__ hW2, const float* __restrict__ hb2,
    const float* __restrict__ hW3, const float* __restrict__ hb3,
    const float* __restrict__ gw2, const float* __restrict__ gb2,
    const float* __restrict__ ga2,
    float* __restrict__ out)
{
    extern __shared__ float smf[];
    float* W1t = smf;                // [128][64]
    float* W2t = W1t + 128 * 64;     // [64][32]
    float* w3  = W2t + 64 * 32;      // [32]
    float* b1  = w3 + 32;            // [64]
    float* b2  = b1 + 64;            // [32]
    float* nsc = b2 + 32;            // [128]
    float* nsh = nsc + 128;          // [128]
    float* hs0 = nsh + 128;          // [2][128][129]

    int tid = threadIdx.x;
    int half = tid >> 7, lt = tid & 127;
    for (int e = tid; e < 8192; e += 256) { int o = e >> 7, k = e & 127; W1t[k * 64 + o] = hW1[e]; }
    for (int e = tid; e < 2048; e += 256) { int o = e >> 6, k = e & 63;  W2t[k * 32 + o] = hW2[e]; }
    if (tid < 32) w3[tid] = hW3[tid];
    if (tid < 64) b1[tid] = hb1[tid];
    if (tid >= 64 && tid < 96) b2[tid - 64] = hb2[tid - 64];
    if (tid < 128) {
        float invn = 1.f / (float)NN;
        float m  = g_stats[2][tid] * invn;
        float e2 = g_stats[2][HH + tid] * invn;
        float a = ga2[tid];
        float var = fmaxf(e2 - m * m * (2.f * a - a * a), 0.f);
        float scale = gw2[tid] * rsqrtf(var + EPSV);
        nsc[tid] = scale;
        nsh[tid] = gb2[tid] - a * m * scale;
    }
    __syncthreads();

    float* hs = hs0 + half * (128 * 129);
    int n0 = blockIdx.x * 256 + half * 128;
    const float4* p4 = (const float4*)g_pre;
    for (int e = lt; e < 128 * 32; e += 128) {
        int r = e >> 5, cc = e & 31;
        int n = n0 + r;
        float4 v = make_float4(0.f, 0.f, 0.f, 0.f);
        if (n < NN) v = p4[n * 32 + cc];
        int c = cc * 4;
        hs[(c + 0) * 129 + r] = gelu_f(v.x * nsc[c + 0] + nsh[c + 0]);
        hs[(c + 1) * 129 + r] = gelu_f(v.y * nsc[c + 1] + nsh[c + 1]);
        hs[(c + 2) * 129 + r] = gelu_f(v.z * nsc[c + 2] + nsh[c + 2]);
        hs[(c + 3) * 129 + r] = gelu_f(v.w * nsc[c + 3] + nsh[c + 3]);
    }
    __syncthreads();

    int n = n0 + lt;
    if (n >= NN) return;

    ull acc1[32];
#pragma unroll
    for (int i = 0; i < 32; i++) acc1[i] = pk2(b1[2 * i], b1[2 * i + 1]);
    for (int k = 0; k < 128; k++) {
        float hv = hs[k * 129 + lt];
        ull a2 = pk2(hv, hv);
        const ull* wr = (const ull*)(W1t + k * 64);
#pragma unroll
        for (int i = 0; i < 32; i++) fma2(acc1[i], a2, wr[i]);
    }
    float y1[64];
#pragma unroll
    for (int i = 0; i < 32; i++) {
        float lo, hi;
        upk2(acc1[i], lo, hi);
        y1[2 * i] = gelu_f(lo);
        y1[2 * i + 1] = gelu_f(hi);
    }
    ull acc2[16];
#pragma unroll
    for (int i = 0; i < 16; i++) acc2[i] = pk2(b2[2 * i], b2[2 * i + 1]);
#pragma unroll 4
    for (int k = 0; k < 64; k++) {
        ull a2 = pk2(y1[k], y1[k]);
        const ull* wr = (const ull*)(W2t + k * 32);
#pragma unroll
        for (int i = 0; i < 16; i++) fma2(acc2[i], a2, wr[i]);
    }
    float s = 0.f;
#pragma unroll
    for (int i = 0; i < 16; i++) {
        float lo, hi;
        upk2(acc2[i], lo, hi);
        s += gelu_f(lo) * w3[2 * i] + gelu_f(hi) * w3[2 * i + 1];
    }
    s += hb3[0];
    out[n] = 1.f / (1.f + expf(-s));
}

// ---------------- launch ----------------
extern "C" void kernel_launch(void* const* d_in, const int* in_sizes, int n_in,
                              void* d_out, int out_size)
{
    const float* x   = (const float*)d_in[0];
    const int*   ei  = (const int*)d_in[1];
    const float* Wl[3] = {(const float*)d_in[2],  (const float*)d_in[8],  (const float*)d_in[14]};
    const float* bl[3] = {(const float*)d_in[3],  (const float*)d_in[9],  (const float*)d_in[15]};
    const float* Wr[3] = {(const float*)d_in[4],  (const float*)d_in[10], (const float*)d_in[16]};
    const float* gw[3] = {(const float*)d_in[5],  (const float*)d_in[11], (const float*)d_in[17]};
    const float* gb[3] = {(const float*)d_in[6],  (const float*)d_in[12], (const float*)d_in[18]};
    const float* ga[3] = {(const float*)d_in[7],  (const float*)d_in[13], (const float*)d_in[19]};
    const float* hW1 = (const float*)d_in[20];
    const float* hb1 = (const float*)d_in[21];
    const float* hW2 = (const float*)d_in[22];
    const float* hb2 = (const float*)d_in[23];
    const float* hW3 = (const float*)d_in[24];
    const float* hb3 = (const float*)d_in[25];
    float* out = (float*)d_out;

    const int SCAN_BLOCKS = (NN + 1023) / 1024;      // 98
    cudaFuncSetAttribute(k_mlp, cudaFuncAttributeMaxDynamicSharedMemorySize, MLP_SMEM);
    cudaFuncSetAttribute(k_gemm_mma, cudaFuncAttributeMaxDynamicSharedMemorySize, MMA_SMEM);

    // CSR build (merged scan)
    k_init<<<(NN + 255) / 256, 256>>>();
    k_hist<<<(EE + 255) / 256, 256>>>(ei);
    k_scan1<<<SCAN_BLOCKS, 1024>>>();
    k_scan3<<<(NN + 255) / 256, 256>>>(SCAN_BLOCKS);
    k_fill<<<(EE + 255) / 256, 256>>>(ei);

    // layer 0
    k_agg20<<<(NN * 32 + 255) / 256, 256>>>(x);
    k_gemm0<<<(NN + 63) / 64, 256>>>(x, Wl[0], bl[0], Wr[0]);

    // layers 1, 2
    for (int L = 1; L <= 2; L++) {
        k_gemm_mma<<<148, 256, MMA_SMEM>>>(Wl[L], Wr[L], gw[L - 1], gb[L - 1], ga[L - 1], L - 1);
        k_aggstats<<<782, 256>>>(bl[L], L);
    }

    // MLP head (2 tiles/block)
    k_mlp<<<(NN + 255) / 256, 256, MLP_SMEM>>>(hW1, hb1, hW2, hb2, hW3, hb3,
                                               gw[2], gb[2], ga[2], out);
}

// round 14
// speedup vs baseline: 1.0498x; 1.0263x over previous
#include <cuda_runtime.h>
#include <cuda_fp16.h>
#include <math.h>

#define NN   100000
#define EE   1600000
#define FIN  20
#define HH   128
#define EPSV 1e-5f
#define NTILES 782            // ceil(NN/128)

// ---------------- scratch ----------------
__device__ __align__(16) unsigned int g_yl8[NN * 32];    // fp8 e4m3 x4: [N][32] uint = 128 ch
__device__ __align__(16) float g_yr[NN * HH];
__device__ __align__(16) float g_pre[NN * HH];
__device__ __align__(16) float g_a20[NN * FIN];
__device__ int   g_deg[NN];
__device__ int   g_off[NN + 1];
__device__ int   g_csr[EE];
__device__ int   g_bsum[128];
__device__ float g_stats[3][2 * HH];

typedef unsigned long long ull;
typedef unsigned int uint;
typedef unsigned short ushort;

__device__ __forceinline__ ull pk2(float lo, float hi) {
    ull r; asm("mov.b64 %0, {%1,%2};" : "=l"(r) : "f"(lo), "f"(hi)); return r;
}
__device__ __forceinline__ void upk2(ull v, float& lo, float& hi) {
    asm("mov.b64 {%0,%1}, %2;" : "=f"(lo), "=f"(hi) : "l"(v));
}
__device__ __forceinline__ void fma2(ull& d, ull a, ull b) {
    asm("fma.rn.f32x2 %0, %1, %2, %0;" : "+l"(d) : "l"(a), "l"(b));
}
__device__ __forceinline__ float gelu_f(float x) {
    return 0.5f * x * (1.0f + erff(x * 0.70710678118654752f));
}
__device__ __forceinline__ uint pack_h2(float lo, float hi) {
    uint r; asm("cvt.rn.f16x2.f32 %0, %2, %1;" : "=r"(r) : "f"(lo), "f"(hi)); return r;
}
__device__ __forceinline__ ushort pack_e4(float lo, float hi) {
    ushort r; asm("cvt.rn.satfinite.e4m3x2.f32 %0, %2, %1;" : "=h"(r) : "f"(lo), "f"(hi));
    return r;
}
// fp8x4 -> two f16x2 accumulators via HADD2 (4 instrs/neighbor-lane)
__device__ __forceinline__ void acc_e4h(uint& aLo, uint& aHi, uint u) {
    uint lo, hi;
    asm("cvt.rn.f16x2.e4m3x2 %0, %1;" : "=r"(lo) : "h"((ushort)(u & 0xffffu)));
    asm("cvt.rn.f16x2.e4m3x2 %0, %1;" : "=r"(hi) : "h"((ushort)(u >> 16)));
    asm("add.rn.f16x2 %0, %0, %1;" : "+r"(aLo) : "r"(lo));
    asm("add.rn.f16x2 %0, %0, %1;" : "+r"(aHi) : "r"(hi));
}
__device__ __forceinline__ void mma_f16(float* d, uint a0, uint a1, uint a2, uint a3,
                                        uint b0, uint b1) {
    asm volatile(
        "mma.sync.aligned.m16n8k16.row.col.f32.f16.f16.f32 "
        "{%0,%1,%2,%3}, {%4,%5,%6,%7}, {%8,%9}, {%0,%1,%2,%3};"
        : "+f"(d[0]), "+f"(d[1]), "+f"(d[2]), "+f"(d[3])
        : "r"(a0), "r"(a1), "r"(a2), "r"(a3), "r"(b0), "r"(b1));
}

// ---------------- init + CSR build ----------------
__global__ void k_init() {
    int i = blockIdx.x * blockDim.x + threadIdx.x;
    if (i < NN) g_deg[i] = 0;
    if (i < 3 * 2 * HH) ((float*)g_stats)[i] = 0.f;
}
__global__ void k_hist(const int* __restrict__ ei) {
    int e = blockIdx.x * blockDim.x + threadIdx.x;
    if (e < EE) atomicAdd(&g_deg[ei[EE + e]], 1);
}
__global__ void k_scan1() {
    __shared__ int s[1024];
    int t = threadIdx.x;
    int i = blockIdx.x * 1024 + t;
    int v = (i < NN) ? g_deg[i] : 0;
    s[t] = v;
    __syncthreads();
#pragma unroll
    for (int d = 1; d < 1024; d <<= 1) {
        int x = (t >= d) ? s[t - d] : 0;
        __syncthreads();
        s[t] += x;
        __syncthreads();
    }
    if (i < NN) g_off[i + 1] = s[t];
    if (t == 1023) g_bsum[blockIdx.x] = s[1023];
}
// merged scan2+scan3 (verified): all 256 threads reach every barrier.
__global__ void k_scan3(int nb) {
    __shared__ int ex[128];
    int t = threadIdx.x;
    int run = 0;
    if (t < 128) {
        run = (t < nb) ? g_bsum[t] : 0;
        ex[t] = run;
    }
    __syncthreads();
#pragma unroll
    for (int d = 1; d < 128; d <<= 1) {
        int x = 0;
        if (t < 128 && t >= d) x = ex[t - d];
        __syncthreads();
        if (t < 128) ex[t] += x;
        __syncthreads();
    }
    if (t < 128) ex[t] -= run;   // exclusive
    __syncthreads();
    int i = blockIdx.x * blockDim.x + t;
    if (i < NN) {
        int tot = g_off[i + 1] + ex[i >> 10];
        g_off[i + 1] = tot;
        int d = g_deg[i];
        g_deg[i] = tot - d;
        if (i == 0) g_off[0] = 0;
    }
}
__global__ void k_fill(const int* __restrict__ ei) {
    int e = blockIdx.x * blockDim.x + threadIdx.x;
    if (e < EE) {
        int d = ei[EE + e];
        int pos = atomicAdd(&g_deg[d], 1);
        g_csr[pos] = ei[e];
    }
}

// ---------------- layer-0 aggregation (20 cols, 1 warp/node) ----------------
__global__ void k_agg20(const float* __restrict__ x) {
    int w = (blockIdx.x * blockDim.x + threadIdx.x) >> 5;
    int lane = threadIdx.x & 31;
    if (w >= NN) return;
    int off = g_off[w], end = g_off[w + 1];
    float acc = 0.f;
    for (int j = off; j < end; j += 32) {
        int idx = (j + lane < end) ? g_csr[j + lane] : 0;
        int cnt = min(32, end - j);
        int t = 0;
        for (; t + 4 <= cnt; t += 4) {
            int s0 = __shfl_sync(0xffffffffu, idx, t);
            int s1 = __shfl_sync(0xffffffffu, idx, t + 1);
            int s2 = __shfl_sync(0xffffffffu, idx, t + 2);
            int s3 = __shfl_sync(0xffffffffu, idx, t + 3);
            if (lane < FIN) {
                float v0 = x[s0 * FIN + lane], v1 = x[s1 * FIN + lane];
                float v2 = x[s2 * FIN + lane], v3 = x[s3 * FIN + lane];
                acc += (v0 + v1) + (v2 + v3);
            }
        }
        for (; t < cnt; t++) {
            int s = __shfl_sync(0xffffffffu, idx, t);
            if (lane < FIN) acc += x[s * FIN + lane];
        }
    }
    if (lane < FIN) {
        int deg = end - off;
        g_a20[w * FIN + lane] = acc * (deg > 0 ? 1.f / (float)deg : 0.f);
    }
}

// ---------------- layer-0 GEMM (K=20) + bias + stats ----------------
__global__ __launch_bounds__(256) void k_gemm0(
    const float* __restrict__ x, const float* __restrict__ Wl,
    const float* __restrict__ bl, const float* __restrict__ Wr)
{
    __shared__ float Wls[FIN][HH], Wrs[FIN][HH], bls[HH];
    __shared__ float As[64][FIN + 1], Xs[64][FIN + 1];
    __shared__ float red[16][HH];
    int tid = threadIdx.x;
    for (int e = tid; e < HH * FIN; e += 256) {
        int o = e / FIN, k = e % FIN;
        Wls[k][o] = Wl[e];
        Wrs[k][o] = Wr[e];
    }
    if (tid < HH) bls[tid] = bl[tid];
    int n0 = blockIdx.x * 64;
    for (int e = tid; e < 64 * FIN; e += 256) {
        int i = e / FIN, k = e % FIN;
        int n = n0 + i;
        As[i][k] = (n < NN) ? g_a20[n * FIN + k] : 0.f;
        Xs[i][k] = (n < NN) ? x[n * FIN + k] : 0.f;
    }
    __syncthreads();
    int tm = tid >> 4, tn = tid & 15;
    ull acc[4][4];
#pragma unroll
    for (int r = 0; r < 4; r++)
#pragma unroll
        for (int c = 0; c < 4; c++)
            acc[r][c] = pk2(bls[tn * 8 + 2 * c], bls[tn * 8 + 2 * c + 1]);
#pragma unroll 4
    for (int k = 0; k < FIN; k++) {
        const ull* wl = (const ull*)&Wls[k][tn * 8];
        const ull* wr = (const ull*)&Wrs[k][tn * 8];
#pragma unroll
        for (int r = 0; r < 4; r++) {
            ull a2 = pk2(As[tm * 4 + r][k], As[tm * 4 + r][k]);
            ull x2 = pk2(Xs[tm * 4 + r][k], Xs[tm * 4 + r][k]);
#pragma unroll
            for (int c = 0; c < 4; c++) { fma2(acc[r][c], a2, wl[c]); fma2(acc[r][c], x2, wr[c]); }
        }
    }
    float av[4][8];
    float s[8] = {0,0,0,0,0,0,0,0}, s2[8] = {0,0,0,0,0,0,0,0};
#pragma unroll
    for (int r = 0; r < 4; r++) {
#pragma unroll
        for (int c = 0; c < 4; c++) upk2(acc[r][c], av[r][2 * c], av[r][2 * c + 1]);
        int n = n0 + tm * 4 + r;
        if (n < NN) {
            float4* o4 = (float4*)(g_pre + n * HH + tn * 8);
            o4[0] = make_float4(av[r][0], av[r][1], av[r][2], av[r][3]);
            o4[1] = make_float4(av[r][4], av[r][5], av[r][6], av[r][7]);
#pragma unroll
            for (int j = 0; j < 8; j++) { s[j] += av[r][j]; s2[j] += av[r][j] * av[r][j]; }
        }
    }
#pragma unroll
    for (int j = 0; j < 8; j++) red[tm][tn * 8 + j] = s[j];
    __syncthreads();
    if (tid < HH) {
        float t = 0.f;
#pragma unroll
        for (int w = 0; w < 16; w++) t += red[w][tid];
        atomicAdd(&g_stats[0][tid], t);
    }
    __syncthreads();
#pragma unroll
    for (int j = 0; j < 8; j++) red[tm][tn * 8 + j] = s2[j];
    __syncthreads();
    if (tid < HH) {
        float t = 0.f;
#pragma unroll
        for (int w = 0; w < 16; w++) t += red[w][tid];
        atomicAdd(&g_stats[0][HH + tid], t);
    }
}

// ---------------- FP16 mma.sync dual GEMM (fragment-order smem layouts) ----------------
#define BF_UINTS (2 * 8 * 8 * 128)
#define AF_UINTS (8 * 8 * 132)
#define OFF_BF   0
#define OFF_AF   (BF_UINTS * 4)
#define OFF_NSC  (OFF_AF + AF_UINTS * 4)
#define OFF_NSH  (OFF_NSC + 512)
#define MMA_SMEM (OFF_NSH + 512)

__global__ __launch_bounds__(256, 1) void k_gemm_mma(
    const float* __restrict__ Wl, const float* __restrict__ Wr,
    const float* __restrict__ gw, const float* __restrict__ gb,
    const float* __restrict__ ga, int Lm1)
{
    extern __shared__ char sm[];
    uint*  Bf  = (uint*)(sm + OFF_BF);
    uint*  Af  = (uint*)(sm + OFF_AF);
    float* nsc = (float*)(sm + OFF_NSC);
    float* nsh = (float*)(sm + OFF_NSH);
    int tid = threadIdx.x;
    int wid = tid >> 5, lane = tid & 31;
    int tq = lane >> 2, tr = lane & 3;
    int rg = wid & 3, cg = wid >> 2;

    if (tid < HH) {
        float invn = 1.f / (float)NN;
        float m  = g_stats[Lm1][tid] * invn;
        float e2 = g_stats[Lm1][HH + tid] * invn;
        float a = ga[tid];
        float var = fmaxf(e2 - m * m * (2.f * a - a * a), 0.f);
        float scale = gw[tid] * rsqrtf(var + EPSV);
        nsc[tid] = scale;
        nsh[tid] = gb[tid] - a * m * scale;
    }

    for (int e = tid; e < 256 * 32; e += 256) {
        int c = e >> 5, c4 = e & 31;
        const float4* src = (const float4*)((c < 128) ? Wl : Wr);
        float4 v = src[(c & 127) * 32 + c4];
        uint h0 = pack_h2(v.x, v.y);
        uint h1 = pack_h2(v.z, v.w);
        int cgi = c >> 7, cl = c & 127;
        int j = cl >> 3, jp = j >> 1, jl = j & 1, nq = cl & 7;
        int p = 2 * c4;
        int k16 = p >> 3, q = p & 7;
        int reg = (q >= 4) ? 1 : 0;
        uint* dst = Bf + (((cgi * 8 + k16) * 8 + jp) << 7) + jl * 2 + reg;
        dst[(nq * 4 + (q & 3)) * 4]       = h0;
        dst[(nq * 4 + ((q + 1) & 3)) * 4] = h1;
    }

    const float4* P4 = (const float4*)g_pre;

    for (int tile = blockIdx.x; tile < NTILES; tile += gridDim.x) {
        int m0 = tile * 128;
        __syncthreads();
        for (int e = tid; e < 128 * 32; e += 256) {
            int r = e >> 5, c4 = e & 31;
            int row = m0 + r;
            float4 v = make_float4(0.f, 0.f, 0.f, 0.f);
            if (row < NN) v = P4[row * 32 + c4];
            int c = c4 * 4;
            float g0 = gelu_f(v.x * nsc[c + 0] + nsh[c + 0]);
            float g1 = gelu_f(v.y * nsc[c + 1] + nsh[c + 1]);
            float g2 = gelu_f(v.z * nsc[c + 2] + nsh[c + 2]);
            float g3 = gelu_f(v.w * nsc[c + 3] + nsh[c + 3]);
            uint h0 = pack_h2(g0, g1);
            uint h1 = pack_h2(g2, g3);
            int rt = r >> 4, rr = r & 15, rh = rr >> 3, tq_ = rr & 7;
            int p = 2 * c4;
            int k16 = p >> 3, q = p & 7;
            int reg = ((q >= 4) ? 2 : 0) + rh;
            uint* dst = Af + (rt * 8 + k16) * 132 + reg;
            dst[(tq_ * 4 + (q & 3)) * 4]       = h0;
            dst[(tq_ * 4 + ((q + 1) & 3)) * 4] = h1;
        }
        __syncthreads();

        int rt0 = rg * 2, rt1 = rg * 2 + 1;
        float acc[2][16][4];
#pragma unroll
        for (int t2 = 0; t2 < 2; t2++)
#pragma unroll
            for (int j = 0; j < 16; j++)
#pragma unroll
                for (int c = 0; c < 4; c++) acc[t2][j][c] = 0.f;

#pragma unroll
        for (int k16 = 0; k16 < 8; k16++) {
            uint4 A0 = ((const uint4*)(Af + (rt0 * 8 + k16) * 132))[lane];
            uint4 A1 = ((const uint4*)(Af + (rt1 * 8 + k16) * 132))[lane];
            const uint4* Bp = (const uint4*)(Bf + (((cg * 8 + k16) * 8) << 7));
#pragma unroll
            for (int jp = 0; jp < 8; jp++) {
                uint4 B = Bp[(jp << 5) + lane];
                mma_f16(acc[0][jp * 2],     A0.x, A0.y, A0.z, A0.w, B.x, B.y);
                mma_f16(acc[1][jp * 2],     A1.x, A1.y, A1.z, A1.w, B.x, B.y);
                mma_f16(acc[0][jp * 2 + 1], A0.x, A0.y, A0.z, A0.w, B.z, B.w);
                mma_f16(acc[1][jp * 2 + 1], A1.x, A1.y, A1.z, A1.w, B.z, B.w);
            }
        }

#pragma unroll
        for (int t2 = 0; t2 < 2; t2++) {
            int row0 = m0 + rg * 32 + t2 * 16 + tq;
            if (cg == 0) {
                ushort* yl8s = (ushort*)g_yl8;
#pragma unroll
                for (int j = 0; j < 16; j++) {
                    int hidx = j * 4 + tr;
                    if (row0 < NN)
                        yl8s[row0 * 64 + hidx] = pack_e4(acc[t2][j][0], acc[t2][j][1]);
                    if (row0 + 8 < NN)
                        yl8s[(row0 + 8) * 64 + hidx] = pack_e4(acc[t2][j][2], acc[t2][j][3]);
                }
            } else {
#pragma unroll
                for (int j = 0; j < 16; j++) {
                    int col = j * 8 + tr * 2;
                    if (row0 < NN)
                        *(float2*)(g_yr + row0 * HH + col) = make_float2(acc[t2][j][0], acc[t2][j][1]);
                    if (row0 + 8 < NN)
                        *(float2*)(g_yr + (row0 + 8) * HH + col) = make_float2(acc[t2][j][2], acc[t2][j][3]);
                }
            }
        }
    }
}

// ---------------- aggregation of yl(fp8, f16x2 accumulate) + add yr + bias + stats ----------------
__global__ __launch_bounds__(256) void k_aggstats(const float* __restrict__ bl, int L)
{
    __shared__ float red[8][HH];
    int tid = threadIdx.x;
    int lane = tid & 31, wp = tid >> 5;
    const uint* yl1 = (const uint*)g_yl8;       // lane covers ch lane*4..+3 (1 uint)
    const float4* yr4 = (const float4*)g_yr;
    float4 bias = ((const float4*)bl)[lane];
    float s[4] = {0, 0, 0, 0}, s2[4] = {0, 0, 0, 0};
    int gw = blockIdx.x * 8 + wp;
    const int stride = gridDim.x * 8;
    for (int w = gw; w < NN; w += stride) {
        int off = g_off[w], end = g_off[w + 1];
        uint aLo = 0u, aHi = 0u;                // two f16x2 accumulators (zero = +0h pairs)
        for (int j = off; j < end; j += 32) {
            int idx = (j + lane < end) ? g_csr[j + lane] : 0;
            int cnt = min(32, end - j);
            int t = 0;
            for (; t + 4 <= cnt; t += 4) {
                int s0 = __shfl_sync(0xffffffffu, idx, t);
                int s1 = __shfl_sync(0xffffffffu, idx, t + 1);
                int s2i = __shfl_sync(0xffffffffu, idx, t + 2);
                int s3 = __shfl_sync(0xffffffffu, idx, t + 3);
                uint u0 = yl1[s0 * 32 + lane];
                uint u1 = yl1[s1 * 32 + lane];
                uint u2 = yl1[s2i * 32 + lane];
                uint u3 = yl1[s3 * 32 + lane];
                acc_e4h(aLo, aHi, u0); acc_e4h(aLo, aHi, u1);
                acc_e4h(aLo, aHi, u2); acc_e4h(aLo, aHi, u3);
            }
            for (; t < cnt; t++) {
                int sx = __shfl_sync(0xffffffffu, idx, t);
                acc_e4h(aLo, aHi, yl1[sx * 32 + lane]);
            }
        }
        float2 fLo = __half22float2(*(__half2*)&aLo);
        float2 fHi = __half22float2(*(__half2*)&aHi);
        int deg = end - off;
        float inv = (deg > 0) ? 1.f / (float)deg : 0.f;
        float4 r = yr4[w * 32 + lane];
        r.x = fLo.x * inv + r.x + bias.x;
        r.y = fLo.y * inv + r.y + bias.y;
        r.z = fHi.x * inv + r.z + bias.z;
        r.w = fHi.y * inv + r.w + bias.w;
        ((float4*)g_pre)[w * 32 + lane] = r;
        s[0] += r.x; s2[0] += r.x * r.x;
        s[1] += r.y; s2[1] += r.y * r.y;
        s[2] += r.z; s2[2] += r.z * r.z;
        s[3] += r.w; s2[3] += r.w * r.w;
    }
#pragma unroll
    for (int i = 0; i < 4; i++) red[wp][lane * 4 + i] = s[i];
    __syncthreads();
    if (tid < HH) {
        float t = 0.f;
#pragma unroll
        for (int w = 0; w < 8; w++) t += red[w][tid];
        atomicAdd(&g_stats[L][tid], t);
    }
    __syncthreads();
#pragma unroll
    for (int i = 0; i < 4; i++) red[wp][lane * 4 + i] = s2[i];
    __syncthreads();
    if (tid < HH) {
        float t = 0.f;
#pragma unroll
        for (int w = 0; w < 8; w++) t += red[w][tid];
        atomicAdd(&g_stats[L][HH + tid], t);
    }
}

// ---------------- fused MLP head: 256 threads, 2 node-tiles/block ----------------
#define MLP_W   (8192 + 2048 + 32 + 64 + 32 + 256)     // weights+consts floats
#define MLP_SMEM ((MLP_W + 2 * 128 * 129) * 4)

__global__ __launch_bounds__(256) void k_mlp(
    const float* __restrict__ hW1, const float* __restrict__ hb1,
    const float* __restrict__ hW2, const float* __restrict__ hb2,
    const float* __restrict__ hW3, const float* __restrict__ hb3,
    const float* __restrict__ gw2, const float* __restrict__ gb2,
    const float* __restrict__ ga2,
    float* __restrict__ out)
{
    extern __shared__ float smf[];
    float* W1t = smf;                // [128][64]
    float* W2t = W1t + 128 * 64;     // [64][32]
    float* w3  = W2t + 64 * 32;      // [32]
    float* b1  = w3 + 32;            // [64]
    float* b2  = b1 + 64;            // [32]
    float* nsc = b2 + 32;            // [128]
    float* nsh = nsc + 128;          // [128]
    float* hs0 = nsh + 128;          // [2][128][129]

    int tid = threadIdx.x;
    int half = tid >> 7, lt = tid & 127;
    for (int e = tid; e < 8192; e += 256) { int o = e >> 7, k = e & 127; W1t[k * 64 + o] = hW1[e]; }
    for (int e = tid; e < 2048; e += 256) { int o = e >> 6, k = e & 63;  W2t[k * 32 + o] = hW2[e]; }
    if (tid < 32) w3[tid] = hW3[tid];
    if (tid < 64) b1[tid] = hb1[tid];
    if (tid >= 64 && tid < 96) b2[tid - 64] = hb2[tid - 64];
    if (tid < 128) {
        float invn = 1.f / (float)NN;
        float m  = g_stats[2][tid] * invn;
        float e2 = g_stats[2][HH + tid] * invn;
        float a = ga2[tid];
        float var = fmaxf(e2 - m * m * (2.f * a - a * a), 0.f);
        float scale = gw2[tid] * rsqrtf(var + EPSV);
        nsc[tid] = scale;
        nsh[tid] = gb2[tid] - a * m * scale;
    }
    __syncthreads();

    float* hs = hs0 + half * (128 * 129);
    int n0 = blockIdx.x * 256 + half * 128;
    const float4* p4 = (const float4*)g_pre;
    for (int e = lt; e < 128 * 32; e += 128) {
        int r = e >> 5, cc = e & 31;
        int n = n0 + r;
        float4 v = make_float4(0.f, 0.f, 0.f, 0.f);
        if (n < NN) v = p4[n * 32 + cc];
        int c = cc * 4;
        hs[(c + 0) * 129 + r] = gelu_f(v.x * nsc[c + 0] + nsh[c + 0]);
        hs[(c + 1) * 129 + r] = gelu_f(v.y * nsc[c + 1] + nsh[c + 1]);
        hs[(c + 2) * 129 + r] = gelu_f(v.z * nsc[c + 2] + nsh[c + 2]);
        hs[(c + 3) * 129 + r] = gelu_f(v.w * nsc[c + 3] + nsh[c + 3]);
    }
    __syncthreads();

    int n = n0 + lt;
    if (n >= NN) return;

    ull acc1[32];
#pragma unroll
    for (int i = 0; i < 32; i++) acc1[i] = pk2(b1[2 * i], b1[2 * i + 1]);
    for (int k = 0; k < 128; k++) {
        float hv = hs[k * 129 + lt];
        ull a2 = pk2(hv, hv);
        const ull* wr = (const ull*)(W1t + k * 64);
#pragma unroll
        for (int i = 0; i < 32; i++) fma2(acc1[i], a2, wr[i]);
    }
    float y1[64];
#pragma unroll
    for (int i = 0; i < 32; i++) {
        float lo, hi;
        upk2(acc1[i], lo, hi);
        y1[2 * i] = gelu_f(lo);
        y1[2 * i + 1] = gelu_f(hi);
    }
    ull acc2[16];
#pragma unroll
    for (int i = 0; i < 16; i++) acc2[i] = pk2(b2[2 * i], b2[2 * i + 1]);
#pragma unroll 4
    for (int k = 0; k < 64; k++) {
        ull a2 = pk2(y1[k], y1[k]);
        const ull* wr = (const ull*)(W2t + k * 32);
#pragma unroll
        for (int i = 0; i < 16; i++) fma2(acc2[i], a2, wr[i]);
    }
    float s = 0.f;
#pragma unroll
    for (int i = 0; i < 16; i++) {
        float lo, hi;
        upk2(acc2[i], lo, hi);
        s += gelu_f(lo) * w3[2 * i] + gelu_f(hi) * w3[2 * i + 1];
    }
    s += hb3[0];
    out[n] = 1.f / (1.f + expf(-s));
}

// ---------------- launch ----------------
extern "C" void kernel_launch(void* const* d_in, const int* in_sizes, int n_in,
                              void* d_out, int out_size)
{
    const float* x   = (const float*)d_in[0];
    const int*   ei  = (const int*)d_in[1];
    const float* Wl[3] = {(const float*)d_in[2],  (const float*)d_in[8],  (const float*)d_in[14]};
    const float* bl[3] = {(const float*)d_in[3],  (const float*)d_in[9],  (const float*)d_in[15]};
    const float* Wr[3] = {(const float*)d_in[4],  (const float*)d_in[10], (const float*)d_in[16]};
    const float* gw[3] = {(const float*)d_in[5],  (const float*)d_in[11], (const float*)d_in[17]};
    const float* gb[3] = {(const float*)d_in[6],  (const float*)d_in[12], (const float*)d_in[18]};
    const float* ga[3] = {(const float*)d_in[7],  (const float*)d_in[13], (const float*)d_in[19]};
    const float* hW1 = (const float*)d_in[20];
    const float* hb1 = (const float*)d_in[21];
    const float* hW2 = (const float*)d_in[22];
    const float* hb2 = (const float*)d_in[23];
    const float* hW3 = (const float*)d_in[24];
    const float* hb3 = (const float*)d_in[25];
    float* out = (float*)d_out;

    const int SCAN_BLOCKS = (NN + 1023) / 1024;      // 98
    cudaFuncSetAttribute(k_mlp, cudaFuncAttributeMaxDynamicSharedMemorySize, MLP_SMEM);
    cudaFuncSetAttribute(k_gemm_mma, cudaFuncAttributeMaxDynamicSharedMemorySize, MMA_SMEM);

    // CSR build (merged scan)
    k_init<<<(NN + 255) / 256, 256>>>();
    k_hist<<<(EE + 255) / 256, 256>>>(ei);
    k_scan1<<<SCAN_BLOCKS, 1024>>>();
    k_scan3<<<(NN + 255) / 256, 256>>>(SCAN_BLOCKS);
    k_fill<<<(EE + 255) / 256, 256>>>(ei);

    // layer 0
    k_agg20<<<(NN * 32 + 255) / 256, 256>>>(x);
    k_gemm0<<<(NN + 63) / 64, 256>>>(x, Wl[0], bl[0], Wr[0]);

    // layers 1, 2
    for (int L = 1; L <= 2; L++) {
        k_gemm_mma<<<148, 256, MMA_SMEM>>>(Wl[L], Wr[L], gw[L - 1], gb[L - 1], ga[L - 1], L - 1);
        k_aggstats<<<782, 256>>>(bl[L], L);
    }

    // MLP head (2 tiles/block)
    k_mlp<<<(NN + 255) / 256, 256, MLP_SMEM>>>(hW1, hb1, hW2, hb2, hW3, hb3,
                                               gw[2], gb[2], ga[2], out);
}

// round 15
// speedup vs baseline: 1.0982x; 1.0462x over previous
#include <cuda_runtime.h>
#include <cuda_fp16.h>
#include <math.h>

#define NN   100000
#define EE   1600000
#define FIN  20
#define HH   128
#define EPSV 1e-5f
#define NTILES 782            // ceil(NN/128)

// ---------------- scratch ----------------
__device__ __align__(16) unsigned int g_yl8[NN * 32];    // fp8 e4m3 x4: [N][32] uint = 128 ch
__device__ __align__(16) unsigned int g_yr16[NN * 64];   // fp16x2: [N][64] uint = 128 ch
__device__ __align__(16) float g_pre[NN * HH];
__device__ __align__(16) float g_a20[NN * FIN];
__device__ __align__(16) unsigned int g_x8[(NN * FIN) / 4];  // x in e4m3 bytes (flat)
__device__ int   g_deg[NN];
__device__ int   g_off[NN + 1];
__device__ int   g_csr[EE];
__device__ int   g_bsum[128];
__device__ float g_stats[3][2 * HH];

typedef unsigned long long ull;
typedef unsigned int uint;
typedef unsigned short ushort;
typedef unsigned char uchar;

__device__ __forceinline__ ull pk2(float lo, float hi) {
    ull r; asm("mov.b64 %0, {%1,%2};" : "=l"(r) : "f"(lo), "f"(hi)); return r;
}
__device__ __forceinline__ void upk2(ull v, float& lo, float& hi) {
    asm("mov.b64 {%0,%1}, %2;" : "=f"(lo), "=f"(hi) : "l"(v));
}
__device__ __forceinline__ void fma2(ull& d, ull a, ull b) {
    asm("fma.rn.f32x2 %0, %1, %2, %0;" : "+l"(d) : "l"(a), "l"(b));
}
__device__ __forceinline__ float gelu_f(float x) {
    return 0.5f * x * (1.0f + erff(x * 0.70710678118654752f));
}
__device__ __forceinline__ uint pack_h2(float lo, float hi) {
    uint r; asm("cvt.rn.f16x2.f32 %0, %2, %1;" : "=r"(r) : "f"(lo), "f"(hi)); return r;
}
__device__ __forceinline__ ushort pack_e4(float lo, float hi) {
    ushort r; asm("cvt.rn.satfinite.e4m3x2.f32 %0, %2, %1;" : "=h"(r) : "f"(lo), "f"(hi));
    return r;
}
// single e4m3 byte -> float
__device__ __forceinline__ float e4b_to_f(uint b) {
    uint h; asm("cvt.rn.f16x2.e4m3x2 %0, %1;" : "=r"(h) : "h"((ushort)b));
    return __half2float(*(__half*)&h);
}
// fp8x4 -> two f16x2 accumulators via HADD2
__device__ __forceinline__ void acc_e4h(uint& aLo, uint& aHi, uint u) {
    uint lo, hi;
    asm("cvt.rn.f16x2.e4m3x2 %0, %1;" : "=r"(lo) : "h"((ushort)(u & 0xffffu)));
    asm("cvt.rn.f16x2.e4m3x2 %0, %1;" : "=r"(hi) : "h"((ushort)(u >> 16)));
    asm("add.rn.f16x2 %0, %0, %1;" : "+r"(aLo) : "r"(lo));
    asm("add.rn.f16x2 %0, %0, %1;" : "+r"(aHi) : "r"(hi));
}
__device__ __forceinline__ void mma_f16(float* d, uint a0, uint a1, uint a2, uint a3,
                                        uint b0, uint b1) {
    asm volatile(
        "mma.sync.aligned.m16n8k16.row.col.f32.f16.f16.f32 "
        "{%0,%1,%2,%3}, {%4,%5,%6,%7}, {%8,%9}, {%0,%1,%2,%3};"
        : "+f"(d[0]), "+f"(d[1]), "+f"(d[2]), "+f"(d[3])
        : "r"(a0), "r"(a1), "r"(a2), "r"(a3), "r"(b0), "r"(b1));
}

// ---------------- init + CSR build ----------------
__global__ void k_init() {
    int i = blockIdx.x * blockDim.x + threadIdx.x;
    if (i < NN) g_deg[i] = 0;
    if (i < 3 * 2 * HH) ((float*)g_stats)[i] = 0.f;
}
__global__ void k_cvt_x(const float* __restrict__ x) {
    int i = blockIdx.x * blockDim.x + threadIdx.x;
    if (i < (NN * FIN) / 4) {
        float4 v = ((const float4*)x)[i];
        g_x8[i] = (uint)pack_e4(v.x, v.y) | ((uint)pack_e4(v.z, v.w) << 16);
    }
}
__global__ void k_hist(const int* __restrict__ ei) {
    int e = blockIdx.x * blockDim.x + threadIdx.x;
    if (e < EE) atomicAdd(&g_deg[ei[EE + e]], 1);
}
__global__ void k_scan1() {
    __shared__ int s[1024];
    int t = threadIdx.x;
    int i = blockIdx.x * 1024 + t;
    int v = (i < NN) ? g_deg[i] : 0;
    s[t] = v;
    __syncthreads();
#pragma unroll
    for (int d = 1; d < 1024; d <<= 1) {
        int x = (t >= d) ? s[t - d] : 0;
        __syncthreads();
        s[t] += x;
        __syncthreads();
    }
    if (i < NN) g_off[i + 1] = s[t];
    if (t == 1023) g_bsum[blockIdx.x] = s[1023];
}
// merged scan2+scan3 (verified): all 256 threads reach every barrier.
__global__ void k_scan3(int nb) {
    __shared__ int ex[128];
    int t = threadIdx.x;
    int run = 0;
    if (t < 128) {
        run = (t < nb) ? g_bsum[t] : 0;
        ex[t] = run;
    }
    __syncthreads();
#pragma unroll
    for (int d = 1; d < 128; d <<= 1) {
        int x = 0;
        if (t < 128 && t >= d) x = ex[t - d];
        __syncthreads();
        if (t < 128) ex[t] += x;
        __syncthreads();
    }
    if (t < 128) ex[t] -= run;   // exclusive
    __syncthreads();
    int i = blockIdx.x * blockDim.x + t;
    if (i < NN) {
        int tot = g_off[i + 1] + ex[i >> 10];
        g_off[i + 1] = tot;
        int d = g_deg[i];
        g_deg[i] = tot - d;
        if (i == 0) g_off[0] = 0;
    }
}
__global__ void k_fill(const int* __restrict__ ei) {
    int e = blockIdx.x * blockDim.x + threadIdx.x;
    if (e < EE) {
        int d = ei[EE + e];
        int pos = atomicAdd(&g_deg[d], 1);
        g_csr[pos] = ei[e];
    }
}

// ---------------- layer-0 aggregation (20 cols fp8, 1 warp/node) ----------------
__global__ void k_agg20() {
    int w = (blockIdx.x * blockDim.x + threadIdx.x) >> 5;
    int lane = threadIdx.x & 31;
    if (w >= NN) return;
    const uchar* xb = (const uchar*)g_x8;
    int off = g_off[w], end = g_off[w + 1];
    float acc = 0.f;
    for (int j = off; j < end; j += 32) {
        int idx = (j + lane < end) ? g_csr[j + lane] : 0;
        int cnt = min(32, end - j);
        int t = 0;
        for (; t + 4 <= cnt; t += 4) {
            int s0 = __shfl_sync(0xffffffffu, idx, t);
            int s1 = __shfl_sync(0xffffffffu, idx, t + 1);
            int s2 = __shfl_sync(0xffffffffu, idx, t + 2);
            int s3 = __shfl_sync(0xffffffffu, idx, t + 3);
            if (lane < FIN) {
                uint b0 = xb[s0 * FIN + lane];
                uint b1 = xb[s1 * FIN + lane];
                uint b2 = xb[s2 * FIN + lane];
                uint b3 = xb[s3 * FIN + lane];
                acc += (e4b_to_f(b0) + e4b_to_f(b1)) + (e4b_to_f(b2) + e4b_to_f(b3));
            }
        }
        for (; t < cnt; t++) {
            int s = __shfl_sync(0xffffffffu, idx, t);
            if (lane < FIN) acc += e4b_to_f(xb[s * FIN + lane]);
        }
    }
    if (lane < FIN) {
        int deg = end - off;
        g_a20[w * FIN + lane] = acc * (deg > 0 ? 1.f / (float)deg : 0.f);
    }
}

// ---------------- layer-0 GEMM (K=20) + bias + stats ----------------
__global__ __launch_bounds__(256) void k_gemm0(
    const float* __restrict__ x, const float* __restrict__ Wl,
    const float* __restrict__ bl, const float* __restrict__ Wr)
{
    __shared__ float Wls[FIN][HH], Wrs[FIN][HH], bls[HH];
    __shared__ float As[64][FIN + 1], Xs[64][FIN + 1];
    __shared__ float red[16][HH];
    int tid = threadIdx.x;
    for (int e = tid; e < HH * FIN; e += 256) {
        int o = e / FIN, k = e % FIN;
        Wls[k][o] = Wl[e];
        Wrs[k][o] = Wr[e];
    }
    if (tid < HH) bls[tid] = bl[tid];
    int n0 = blockIdx.x * 64;
    for (int e = tid; e < 64 * FIN; e += 256) {
        int i = e / FIN, k = e % FIN;
        int n = n0 + i;
        As[i][k] = (n < NN) ? g_a20[n * FIN + k] : 0.f;
        Xs[i][k] = (n < NN) ? x[n * FIN + k] : 0.f;
    }
    __syncthreads();
    int tm = tid >> 4, tn = tid & 15;
    ull acc[4][4];
#pragma unroll
    for (int r = 0; r < 4; r++)
#pragma unroll
        for (int c = 0; c < 4; c++)
            acc[r][c] = pk2(bls[tn * 8 + 2 * c], bls[tn * 8 + 2 * c + 1]);
#pragma unroll 4
    for (int k = 0; k < FIN; k++) {
        const ull* wl = (const ull*)&Wls[k][tn * 8];
        const ull* wr = (const ull*)&Wrs[k][tn * 8];
#pragma unroll
        for (int r = 0; r < 4; r++) {
            ull a2 = pk2(As[tm * 4 + r][k], As[tm * 4 + r][k]);
            ull x2 = pk2(Xs[tm * 4 + r][k], Xs[tm * 4 + r][k]);
#pragma unroll
            for (int c = 0; c < 4; c++) { fma2(acc[r][c], a2, wl[c]); fma2(acc[r][c], x2, wr[c]); }
        }
    }
    float av[4][8];
    float s[8] = {0,0,0,0,0,0,0,0}, s2[8] = {0,0,0,0,0,0,0,0};
#pragma unroll
    for (int r = 0; r < 4; r++) {
#pragma unroll
        for (int c = 0; c < 4; c++) upk2(acc[r][c], av[r][2 * c], av[r][2 * c + 1]);
        int n = n0 + tm * 4 + r;
        if (n < NN) {
            float4* o4 = (float4*)(g_pre + n * HH + tn * 8);
            o4[0] = make_float4(av[r][0], av[r][1], av[r][2], av[r][3]);
            o4[1] = make_float4(av[r][4], av[r][5], av[r][6], av[r][7]);
#pragma unroll
            for (int j = 0; j < 8; j++) { s[j] += av[r][j]; s2[j] += av[r][j] * av[r][j]; }
        }
    }
#pragma unroll
    for (int j = 0; j < 8; j++) red[tm][tn * 8 + j] = s[j];
    __syncthreads();
    if (tid < HH) {
        float t = 0.f;
#pragma unroll
        for (int w = 0; w < 16; w++) t += red[w][tid];
        atomicAdd(&g_stats[0][tid], t);
    }
    __syncthreads();
#pragma unroll
    for (int j = 0; j < 8; j++) red[tm][tn * 8 + j] = s2[j];
    __syncthreads();
    if (tid < HH) {
        float t = 0.f;
#pragma unroll
        for (int w = 0; w < 16; w++) t += red[w][tid];
        atomicAdd(&g_stats[0][HH + tid], t);
    }
}

// ---------------- FP16 mma.sync dual GEMM (fragment-order smem layouts) ----------------
#define BF_UINTS (2 * 8 * 8 * 128)
#define AF_UINTS (8 * 8 * 132)
#define OFF_BF   0
#define OFF_AF   (BF_UINTS * 4)
#define OFF_NSC  (OFF_AF + AF_UINTS * 4)
#define OFF_NSH  (OFF_NSC + 512)
#define MMA_SMEM (OFF_NSH + 512)

__global__ __launch_bounds__(256, 1) void k_gemm_mma(
    const float* __restrict__ Wl, const float* __restrict__ Wr,
    const float* __restrict__ gw, const float* __restrict__ gb,
    const float* __restrict__ ga, int Lm1)
{
    extern __shared__ char sm[];
    uint*  Bf  = (uint*)(sm + OFF_BF);
    uint*  Af  = (uint*)(sm + OFF_AF);
    float* nsc = (float*)(sm + OFF_NSC);
    float* nsh = (float*)(sm + OFF_NSH);
    int tid = threadIdx.x;
    int wid = tid >> 5, lane = tid & 31;
    int tq = lane >> 2, tr = lane & 3;
    int rg = wid & 3, cg = wid >> 2;

    if (tid < HH) {
        float invn = 1.f / (float)NN;
        float m  = g_stats[Lm1][tid] * invn;
        float e2 = g_stats[Lm1][HH + tid] * invn;
        float a = ga[tid];
        float var = fmaxf(e2 - m * m * (2.f * a - a * a), 0.f);
        float scale = gw[tid] * rsqrtf(var + EPSV);
        nsc[tid] = scale;
        nsh[tid] = gb[tid] - a * m * scale;
    }

    for (int e = tid; e < 256 * 32; e += 256) {
        int c = e >> 5, c4 = e & 31;
        const float4* src = (const float4*)((c < 128) ? Wl : Wr);
        float4 v = src[(c & 127) * 32 + c4];
        uint h0 = pack_h2(v.x, v.y);
        uint h1 = pack_h2(v.z, v.w);
        int cgi = c >> 7, cl = c & 127;
        int j = cl >> 3, jp = j >> 1, jl = j & 1, nq = cl & 7;
        int p = 2 * c4;
        int k16 = p >> 3, q = p & 7;
        int reg = (q >= 4) ? 1 : 0;
        uint* dst = Bf + (((cgi * 8 + k16) * 8 + jp) << 7) + jl * 2 + reg;
        dst[(nq * 4 + (q & 3)) * 4]       = h0;
        dst[(nq * 4 + ((q + 1) & 3)) * 4] = h1;
    }

    const float4* P4 = (const float4*)g_pre;

    for (int tile = blockIdx.x; tile < NTILES; tile += gridDim.x) {
        int m0 = tile * 128;
        __syncthreads();
        for (int e = tid; e < 128 * 32; e += 256) {
            int r = e >> 5, c4 = e & 31;
            int row = m0 + r;
            float4 v = make_float4(0.f, 0.f, 0.f, 0.f);
            if (row < NN) v = P4[row * 32 + c4];
            int c = c4 * 4;
            float g0 = gelu_f(v.x * nsc[c + 0] + nsh[c + 0]);
            float g1 = gelu_f(v.y * nsc[c + 1] + nsh[c + 1]);
            float g2 = gelu_f(v.z * nsc[c + 2] + nsh[c + 2]);
            float g3 = gelu_f(v.w * nsc[c + 3] + nsh[c + 3]);
            uint h0 = pack_h2(g0, g1);
            uint h1 = pack_h2(g2, g3);
            int rt = r >> 4, rr = r & 15, rh = rr >> 3, tq_ = rr & 7;
            int p = 2 * c4;
            int k16 = p >> 3, q = p & 7;
            int reg = ((q >= 4) ? 2 : 0) + rh;
            uint* dst = Af + (rt * 8 + k16) * 132 + reg;
            dst[(tq_ * 4 + (q & 3)) * 4]       = h0;
            dst[(tq_ * 4 + ((q + 1) & 3)) * 4] = h1;
        }
        __syncthreads();

        int rt0 = rg * 2, rt1 = rg * 2 + 1;
        float acc[2][16][4];
#pragma unroll
        for (int t2 = 0; t2 < 2; t2++)
#pragma unroll
            for (int j = 0; j < 16; j++)
#pragma unroll
                for (int c = 0; c < 4; c++) acc[t2][j][c] = 0.f;

#pragma unroll
        for (int k16 = 0; k16 < 8; k16++) {
            uint4 A0 = ((const uint4*)(Af + (rt0 * 8 + k16) * 132))[lane];
            uint4 A1 = ((const uint4*)(Af + (rt1 * 8 + k16) * 132))[lane];
            const uint4* Bp = (const uint4*)(Bf + (((cg * 8 + k16) * 8) << 7));
#pragma unroll
            for (int jp = 0; jp < 8; jp++) {
                uint4 B = Bp[(jp << 5) + lane];
                mma_f16(acc[0][jp * 2],     A0.x, A0.y, A0.z, A0.w, B.x, B.y);
                mma_f16(acc[1][jp * 2],     A1.x, A1.y, A1.z, A1.w, B.x, B.y);
                mma_f16(acc[0][jp * 2 + 1], A0.x, A0.y, A0.z, A0.w, B.z, B.w);
                mma_f16(acc[1][jp * 2 + 1], A1.x, A1.y, A1.z, A1.w, B.z, B.w);
            }
        }

#pragma unroll
        for (int t2 = 0; t2 < 2; t2++) {
            int row0 = m0 + rg * 32 + t2 * 16 + tq;
            if (cg == 0) {
                ushort* yl8s = (ushort*)g_yl8;
#pragma unroll
                for (int j = 0; j < 16; j++) {
                    int hidx = j * 4 + tr;
                    if (row0 < NN)
                        yl8s[row0 * 64 + hidx] = pack_e4(acc[t2][j][0], acc[t2][j][1]);
                    if (row0 + 8 < NN)
                        yl8s[(row0 + 8) * 64 + hidx] = pack_e4(acc[t2][j][2], acc[t2][j][3]);
                }
            } else {
#pragma unroll
                for (int j = 0; j < 16; j++) {
                    int hidx = j * 4 + tr;     // uint index (cols j*8+tr*2, +1)
                    if (row0 < NN)
                        g_yr16[row0 * 64 + hidx] = pack_h2(acc[t2][j][0], acc[t2][j][1]);
                    if (row0 + 8 < NN)
                        g_yr16[(row0 + 8) * 64 + hidx] = pack_h2(acc[t2][j][2], acc[t2][j][3]);
                }
            }
        }
    }
}

// ---------------- aggregation of yl(fp8, f16x2 accumulate) + add yr(fp16) + bias + stats ----------------
__global__ __launch_bounds__(256) void k_aggstats(const float* __restrict__ bl, int L)
{
    __shared__ float red[8][HH];
    int tid = threadIdx.x;
    int lane = tid & 31, wp = tid >> 5;
    const uint* yl1 = (const uint*)g_yl8;        // lane covers ch lane*4..+3 (1 uint)
    const uint2* yr2 = (const uint2*)g_yr16;     // lane covers ch lane*4..+3 (uint2)
    float4 bias = ((const float4*)bl)[lane];
    float s[4] = {0, 0, 0, 0}, s2[4] = {0, 0, 0, 0};
    int gw = blockIdx.x * 8 + wp;
    const int stride = gridDim.x * 8;
    for (int w = gw; w < NN; w += stride) {
        int off = g_off[w], end = g_off[w + 1];
        uint aLo = 0u, aHi = 0u;                 // two f16x2 accumulators
        for (int j = off; j < end; j += 32) {
            int idx = (j + lane < end) ? g_csr[j + lane] : 0;
            int cnt = min(32, end - j);
            int t = 0;
            for (; t + 4 <= cnt; t += 4) {
                int s0 = __shfl_sync(0xffffffffu, idx, t);
                int s1 = __shfl_sync(0xffffffffu, idx, t + 1);
                int s2i = __shfl_sync(0xffffffffu, idx, t + 2);
                int s3 = __shfl_sync(0xffffffffu, idx, t + 3);
                uint u0 = yl1[s0 * 32 + lane];
                uint u1 = yl1[s1 * 32 + lane];
                uint u2 = yl1[s2i * 32 + lane];
                uint u3 = yl1[s3 * 32 + lane];
                acc_e4h(aLo, aHi, u0); acc_e4h(aLo, aHi, u1);
                acc_e4h(aLo, aHi, u2); acc_e4h(aLo, aHi, u3);
            }
            for (; t < cnt; t++) {
                int sx = __shfl_sync(0xffffffffu, idx, t);
                acc_e4h(aLo, aHi, yl1[sx * 32 + lane]);
            }
        }
        float2 fLo = __half22float2(*(__half2*)&aLo);
        float2 fHi = __half22float2(*(__half2*)&aHi);
        int deg = end - off;
        float inv = (deg > 0) ? 1.f / (float)deg : 0.f;
        uint2 u = yr2[w * 32 + lane];
        float2 rLo = __half22float2(*(__half2*)&u.x);
        float2 rHi = __half22float2(*(__half2*)&u.y);
        float4 r;
        r.x = fLo.x * inv + rLo.x + bias.x;
        r.y = fLo.y * inv + rLo.y + bias.y;
        r.z = fHi.x * inv + rHi.x + bias.z;
        r.w = fHi.y * inv + rHi.y + bias.w;
        ((float4*)g_pre)[w * 32 + lane] = r;
        s[0] += r.x; s2[0] += r.x * r.x;
        s[1] += r.y; s2[1] += r.y * r.y;
        s[2] += r.z; s2[2] += r.z * r.z;
        s[3] += r.w; s2[3] += r.w * r.w;
    }
#pragma unroll
    for (int i = 0; i < 4; i++) red[wp][lane * 4 + i] = s[i];
    __syncthreads();
    if (tid < HH) {
        float t = 0.f;
#pragma unroll
        for (int w = 0; w < 8; w++) t += red[w][tid];
        atomicAdd(&g_stats[L][tid], t);
    }
    __syncthreads();
#pragma unroll
    for (int i = 0; i < 4; i++) red[wp][lane * 4 + i] = s2[i];
    __syncthreads();
    if (tid < HH) {
        float t = 0.f;
#pragma unroll
        for (int w = 0; w < 8; w++) t += red[w][tid];
        atomicAdd(&g_stats[L][HH + tid], t);
    }
}

// ---------------- fused MLP head: 256 threads, 2 node-tiles/block ----------------
#define MLP_W   (8192 + 2048 + 32 + 64 + 32 + 256)     // weights+consts floats
#define MLP_SMEM ((MLP_W + 2 * 128 * 129) * 4)

__global__ __launch_bounds__(256) void k_mlp(
    const float* __restrict__ hW1, const float* __restrict__ hb1,
    const float* __restrict__ hW2, const float* __restrict__ hb2,
    const float* __restrict__ hW3, const float* __restrict__ hb3,
    const float* __restrict__ gw2, const float* __restrict__ gb2,
    const float* __restrict__ ga2,
    float* __restrict__ out)
{
    extern __shared__ float smf[];
    float* W1t = smf;                // [128][64]
    float* W2t = W1t + 128 * 64;     // [64][32]
    float* w3  = W2t + 64 * 32;      // [32]
    float* b1  = w3 + 32;            // [64]
    float* b2  = b1 + 64;            // [32]
    float* nsc = b2 + 32;            // [128]
    float* nsh = nsc + 128;          // [128]
    float* hs0 = nsh + 128;          // [2][128][129]

    int tid = threadIdx.x;
    int half = tid >> 7, lt = tid & 127;
    for (int e = tid; e < 8192; e += 256) { int o = e >> 7, k = e & 127; W1t[k * 64 + o] = hW1[e]; }
    for (int e = tid; e < 2048; e += 256) { int o = e >> 6, k = e & 63;  W2t[k * 32 + o] = hW2[e]; }
    if (tid < 32) w3[tid] = hW3[tid];
    if (tid < 64) b1[tid] = hb1[tid];
    if (tid >= 64 && tid < 96) b2[tid - 64] = hb2[tid - 64];
    if (tid < 128) {
        float invn = 1.f / (float)NN;
        float m  = g_stats[2][tid] * invn;
        float e2 = g_stats[2][HH + tid] * invn;
        float a = ga2[tid];
        float var = fmaxf(e2 - m * m * (2.f * a - a * a), 0.f);
        float scale = gw2[tid] * rsqrtf(var + EPSV);
        nsc[tid] = scale;
        nsh[tid] = gb2[tid] - a * m * scale;
    }
    __syncthreads();

    float* hs = hs0 + half * (128 * 129);
    int n0 = blockIdx.x * 256 + half * 128;
    const float4* p4 = (const float4*)g_pre;
    for (int e = lt; e < 128 * 32; e += 128) {
        int r = e >> 5, cc = e & 31;
        int n = n0 + r;
        float4 v = make_float4(0.f, 0.f, 0.f, 0.f);
        if (n < NN) v = p4[n * 32 + cc];
        int c = cc * 4;
        hs[(c + 0) * 129 + r] = gelu_f(v.x * nsc[c + 0] + nsh[c + 0]);
        hs[(c + 1) * 129 + r] = gelu_f(v.y * nsc[c + 1] + nsh[c + 1]);
        hs[(c + 2) * 129 + r] = gelu_f(v.z * nsc[c + 2] + nsh[c + 2]);
        hs[(c + 3) * 129 + r] = gelu_f(v.w * nsc[c + 3] + nsh[c + 3]);
    }
    __syncthreads();

    int n = n0 + lt;
    if (n >= NN) return;

    ull acc1[32];
#pragma unroll
    for (int i = 0; i < 32; i++) acc1[i] = pk2(b1[2 * i], b1[2 * i + 1]);
    for (int k = 0; k < 128; k++) {
        float hv = hs[k * 129 + lt];
        ull a2 = pk2(hv, hv);
        const ull* wr = (const ull*)(W1t + k * 64);
#pragma unroll
        for (int i = 0; i < 32; i++) fma2(acc1[i], a2, wr[i]);
    }
    float y1[64];
#pragma unroll
    for (int i = 0; i < 32; i++) {
        float lo, hi;
        upk2(acc1[i], lo, hi);
        y1[2 * i] = gelu_f(lo);
        y1[2 * i + 1] = gelu_f(hi);
    }
    ull acc2[16];
#pragma unroll
    for (int i = 0; i < 16; i++) acc2[i] = pk2(b2[2 * i], b2[2 * i + 1]);
#pragma unroll 4
    for (int k = 0; k < 64; k++) {
        ull a2 = pk2(y1[k], y1[k]);
        const ull* wr = (const ull*)(W2t + k * 32);
#pragma unroll
        for (int i = 0; i < 16; i++) fma2(acc2[i], a2, wr[i]);
    }
    float s = 0.f;
#pragma unroll
    for (int i = 0; i < 16; i++) {
        float lo, hi;
        upk2(acc2[i], lo, hi);
        s += gelu_f(lo) * w3[2 * i] + gelu_f(hi) * w3[2 * i + 1];
    }
    s += hb3[0];
    out[n] = 1.f / (1.f + expf(-s));
}

// ---------------- launch ----------------
extern "C" void kernel_launch(void* const* d_in, const int* in_sizes, int n_in,
                              void* d_out, int out_size)
{
    const float* x   = (const float*)d_in[0];
    const int*   ei  = (const int*)d_in[1];
    const float* Wl[3] = {(const float*)d_in[2],  (const float*)d_in[8],  (const float*)d_in[14]};
    const float* bl[3] = {(const float*)d_in[3],  (const float*)d_in[9],  (const float*)d_in[15]};
    const float* Wr[3] = {(const float*)d_in[4],  (const float*)d_in[10], (const float*)d_in[16]};
    const float* gw[3] = {(const float*)d_in[5],  (const float*)d_in[11], (const float*)d_in[17]};
    const float* gb[3] = {(const float*)d_in[6],  (const float*)d_in[12], (const float*)d_in[18]};
    const float* ga[3] = {(const float*)d_in[7],  (const float*)d_in[13], (const float*)d_in[19]};
    const float* hW1 = (const float*)d_in[20];
    const float* hb1 = (const float*)d_in[21];
    const float* hW2 = (const float*)d_in[22];
    const float* hb2 = (const float*)d_in[23];
    const float* hW3 = (const float*)d_in[24];
    const float* hb3 = (const float*)d_in[25];
    float* out = (float*)d_out;

    const int SCAN_BLOCKS = (NN + 1023) / 1024;      // 98
    cudaFuncSetAttribute(k_mlp, cudaFuncAttributeMaxDynamicSharedMemorySize, MLP_SMEM);
    cudaFuncSetAttribute(k_gemm_mma, cudaFuncAttributeMaxDynamicSharedMemorySize, MMA_SMEM);

    // CSR build (merged scan) + x conversion
    k_init<<<(NN + 255) / 256, 256>>>();
    k_cvt_x<<<(NN * FIN / 4 + 255) / 256, 256>>>(x);
    k_hist<<<(EE + 255) / 256, 256>>>(ei);
    k_scan1<<<SCAN_BLOCKS, 1024>>>();
    k_scan3<<<(NN + 255) / 256, 256>>>(SCAN_BLOCKS);
    k_fill<<<(EE + 255) / 256, 256>>>(ei);

    // layer 0
    k_agg20<<<(NN * 32 + 255) / 256, 256>>>();
    k_gemm0<<<(NN + 63) / 64, 256>>>(x, Wl[0], bl[0], Wr[0]);

    // layers 1, 2
    for (int L = 1; L <= 2; L++) {
        k_gemm_mma<<<148, 256, MMA_SMEM>>>(Wl[L], Wr[L], gw[L - 1], gb[L - 1], ga[L - 1], L - 1);
        k_aggstats<<<782, 256>>>(bl[L], L);
    }

    // MLP head (2 tiles/block)
    k_mlp<<<(NN + 255) / 256, 256, MLP_SMEM>>>(hW1, hb1, hW2, hb2, hW3, hb3,
                                               gw[2], gb[2], ga[2], out);
}

// round 16
// speedup vs baseline: 1.1549x; 1.0516x over previous
#include <cuda_runtime.h>
#include <cuda_fp16.h>
#include <math.h>

#define NN   100000
#define EE   1600000
#define FIN  20
#define HH   128
#define EPSV 1e-5f
#define NTILES 782            // ceil(NN/128)

// ---------------- scratch ----------------
__device__ __align__(16) unsigned int g_yl8[NN * 32];    // fp8 e4m3 x4: [N][32] uint = 128 ch
__device__ __align__(16) unsigned int g_yr16[NN * 64];   // fp16x2: [N][64] uint = 128 ch
__device__ __align__(16) unsigned int g_pre16[NN * 64];  // fp16x2: [N][64] uint = 128 ch
__device__ __align__(16) float g_a20[NN * FIN];
__device__ __align__(16) unsigned int g_x8[(NN * FIN) / 4];  // x in e4m3 bytes (flat)
__device__ int   g_deg[NN];
__device__ int   g_off[NN + 1];
__device__ int   g_csr[EE];
__device__ int   g_bsum[128];
__device__ float g_stats[3][2 * HH];

typedef unsigned long long ull;
typedef unsigned int uint;
typedef unsigned short ushort;
typedef unsigned char uchar;

__device__ __forceinline__ ull pk2(float lo, float hi) {
    ull r; asm("mov.b64 %0, {%1,%2};" : "=l"(r) : "f"(lo), "f"(hi)); return r;
}
__device__ __forceinline__ void upk2(ull v, float& lo, float& hi) {
    asm("mov.b64 {%0,%1}, %2;" : "=f"(lo), "=f"(hi) : "l"(v));
}
__device__ __forceinline__ void fma2(ull& d, ull a, ull b) {
    asm("fma.rn.f32x2 %0, %1, %2, %0;" : "+l"(d) : "l"(a), "l"(b));
}
__device__ __forceinline__ float gelu_f(float x) {
    return 0.5f * x * (1.0f + erff(x * 0.70710678118654752f));
}
__device__ __forceinline__ uint pack_h2(float lo, float hi) {
    uint r; asm("cvt.rn.f16x2.f32 %0, %2, %1;" : "=r"(r) : "f"(lo), "f"(hi)); return r;
}
__device__ __forceinline__ ushort pack_e4(float lo, float hi) {
    ushort r; asm("cvt.rn.satfinite.e4m3x2.f32 %0, %2, %1;" : "=h"(r) : "f"(lo), "f"(hi));
    return r;
}
// single e4m3 byte -> float
__device__ __forceinline__ float e4b_to_f(uint b) {
    uint h; asm("cvt.rn.f16x2.e4m3x2 %0, %1;" : "=r"(h) : "h"((ushort)b));
    return __half2float(*(__half*)&h);
}
// fp8x4 -> two f16x2 accumulators via HADD2
__device__ __forceinline__ void acc_e4h(uint& aLo, uint& aHi, uint u) {
    uint lo, hi;
    asm("cvt.rn.f16x2.e4m3x2 %0, %1;" : "=r"(lo) : "h"((ushort)(u & 0xffffu)));
    asm("cvt.rn.f16x2.e4m3x2 %0, %1;" : "=r"(hi) : "h"((ushort)(u >> 16)));
    asm("add.rn.f16x2 %0, %0, %1;" : "+r"(aLo) : "r"(lo));
    asm("add.rn.f16x2 %0, %0, %1;" : "+r"(aHi) : "r"(hi));
}
__device__ __forceinline__ void mma_f16(float* d, uint a0, uint a1, uint a2, uint a3,
                                        uint b0, uint b1) {
    asm volatile(
        "mma.sync.aligned.m16n8k16.row.col.f32.f16.f16.f32 "
        "{%0,%1,%2,%3}, {%4,%5,%6,%7}, {%8,%9}, {%0,%1,%2,%3};"
        : "+f"(d[0]), "+f"(d[1]), "+f"(d[2]), "+f"(d[3])
        : "r"(a0), "r"(a1), "r"(a2), "r"(a3), "r"(b0), "r"(b1));
}
// unpack uint2 (4 fp16 channels) -> float4
__device__ __forceinline__ float4 up4(uint2 u) {
    float2 lo = __half22float2(*(__half2*)&u.x);
    float2 hi = __half22float2(*(__half2*)&u.y);
    return make_float4(lo.x, lo.y, hi.x, hi.y);
}

// ---------------- init + CSR build ----------------
__global__ void k_init() {
    int i = blockIdx.x * blockDim.x + threadIdx.x;
    if (i < NN) g_deg[i] = 0;
    if (i < 3 * 2 * HH) ((float*)g_stats)[i] = 0.f;
}
__global__ void k_cvt_x(const float* __restrict__ x) {
    int i = blockIdx.x * blockDim.x + threadIdx.x;
    if (i < (NN * FIN) / 4) {
        float4 v = ((const float4*)x)[i];
        g_x8[i] = (uint)pack_e4(v.x, v.y) | ((uint)pack_e4(v.z, v.w) << 16);
    }
}
__global__ void k_hist(const int* __restrict__ ei) {
    int e = blockIdx.x * blockDim.x + threadIdx.x;
    if (e < EE) atomicAdd(&g_deg[ei[EE + e]], 1);
}
__global__ void k_scan1() {
    __shared__ int s[1024];
    int t = threadIdx.x;
    int i = blockIdx.x * 1024 + t;
    int v = (i < NN) ? g_deg[i] : 0;
    s[t] = v;
    __syncthreads();
#pragma unroll
    for (int d = 1; d < 1024; d <<= 1) {
        int x = (t >= d) ? s[t - d] : 0;
        __syncthreads();
        s[t] += x;
        __syncthreads();
    }
    if (i < NN) g_off[i + 1] = s[t];
    if (t == 1023) g_bsum[blockIdx.x] = s[1023];
}
// merged scan2+scan3 (verified): all 256 threads reach every barrier.
__global__ void k_scan3(int nb) {
    __shared__ int ex[128];
    int t = threadIdx.x;
    int run = 0;
    if (t < 128) {
        run = (t < nb) ? g_bsum[t] : 0;
        ex[t] = run;
    }
    __syncthreads();
#pragma unroll
    for (int d = 1; d < 128; d <<= 1) {
        int x = 0;
        if (t < 128 && t >= d) x = ex[t - d];
        __syncthreads();
        if (t < 128) ex[t] += x;
        __syncthreads();
    }
    if (t < 128) ex[t] -= run;   // exclusive
    __syncthreads();
    int i = blockIdx.x * blockDim.x + t;
    if (i < NN) {
        int tot = g_off[i + 1] + ex[i >> 10];
        g_off[i + 1] = tot;
        int d = g_deg[i];
        g_deg[i] = tot - d;
        if (i == 0) g_off[0] = 0;
    }
}
__global__ void k_fill(const int* __restrict__ ei) {
    int e = blockIdx.x * blockDim.x + threadIdx.x;
    if (e < EE) {
        int d = ei[EE + e];
        int pos = atomicAdd(&g_deg[d], 1);
        g_csr[pos] = ei[e];
    }
}

// ---------------- layer-0 aggregation (20 cols fp8, 1 warp/node) ----------------
__global__ void k_agg20() {
    int w = (blockIdx.x * blockDim.x + threadIdx.x) >> 5;
    int lane = threadIdx.x & 31;
    if (w >= NN) return;
    const uchar* xb = (const uchar*)g_x8;
    int off = g_off[w], end = g_off[w + 1];
    float acc = 0.f;
    for (int j = off; j < end; j += 32) {
        int idx = (j + lane < end) ? g_csr[j + lane] : 0;
        int cnt = min(32, end - j);
        int t = 0;
        for (; t + 4 <= cnt; t += 4) {
            int s0 = __shfl_sync(0xffffffffu, idx, t);
            int s1 = __shfl_sync(0xffffffffu, idx, t + 1);
            int s2 = __shfl_sync(0xffffffffu, idx, t + 2);
            int s3 = __shfl_sync(0xffffffffu, idx, t + 3);
            if (lane < FIN) {
                uint b0 = xb[s0 * FIN + lane];
                uint b1 = xb[s1 * FIN + lane];
                uint b2 = xb[s2 * FIN + lane];
                uint b3 = xb[s3 * FIN + lane];
                acc += (e4b_to_f(b0) + e4b_to_f(b1)) + (e4b_to_f(b2) + e4b_to_f(b3));
            }
        }
        for (; t < cnt; t++) {
            int s = __shfl_sync(0xffffffffu, idx, t);
            if (lane < FIN) acc += e4b_to_f(xb[s * FIN + lane]);
        }
    }
    if (lane < FIN) {
        int deg = end - off;
        g_a20[w * FIN + lane] = acc * (deg > 0 ? 1.f / (float)deg : 0.f);
    }
}

// ---------------- layer-0 GEMM (K=20) + bias + stats (pre in fp16) ----------------
__global__ __launch_bounds__(256) void k_gemm0(
    const float* __restrict__ x, const float* __restrict__ Wl,
    const float* __restrict__ bl, const float* __restrict__ Wr)
{
    __shared__ float Wls[FIN][HH], Wrs[FIN][HH], bls[HH];
    __shared__ float As[64][FIN + 1], Xs[64][FIN + 1];
    __shared__ float red[16][HH];
    int tid = threadIdx.x;
    for (int e = tid; e < HH * FIN; e += 256) {
        int o = e / FIN, k = e % FIN;
        Wls[k][o] = Wl[e];
        Wrs[k][o] = Wr[e];
    }
    if (tid < HH) bls[tid] = bl[tid];
    int n0 = blockIdx.x * 64;
    for (int e = tid; e < 64 * FIN; e += 256) {
        int i = e / FIN, k = e % FIN;
        int n = n0 + i;
        As[i][k] = (n < NN) ? g_a20[n * FIN + k] : 0.f;
        Xs[i][k] = (n < NN) ? x[n * FIN + k] : 0.f;
    }
    __syncthreads();
    int tm = tid >> 4, tn = tid & 15;
    ull acc[4][4];
#pragma unroll
    for (int r = 0; r < 4; r++)
#pragma unroll
        for (int c = 0; c < 4; c++)
            acc[r][c] = pk2(bls[tn * 8 + 2 * c], bls[tn * 8 + 2 * c + 1]);
#pragma unroll 4
    for (int k = 0; k < FIN; k++) {
        const ull* wl = (const ull*)&Wls[k][tn * 8];
        const ull* wr = (const ull*)&Wrs[k][tn * 8];
#pragma unroll
        for (int r = 0; r < 4; r++) {
            ull a2 = pk2(As[tm * 4 + r][k], As[tm * 4 + r][k]);
            ull x2 = pk2(Xs[tm * 4 + r][k], Xs[tm * 4 + r][k]);
#pragma unroll
            for (int c = 0; c < 4; c++) { fma2(acc[r][c], a2, wl[c]); fma2(acc[r][c], x2, wr[c]); }
        }
    }
    float av[4][8];
    float s[8] = {0,0,0,0,0,0,0,0}, s2[8] = {0,0,0,0,0,0,0,0};
#pragma unroll
    for (int r = 0; r < 4; r++) {
#pragma unroll
        for (int c = 0; c < 4; c++) upk2(acc[r][c], av[r][2 * c], av[r][2 * c + 1]);
        int n = n0 + tm * 4 + r;
        if (n < NN) {
            uint4 pk;
            pk.x = pack_h2(av[r][0], av[r][1]);
            pk.y = pack_h2(av[r][2], av[r][3]);
            pk.z = pack_h2(av[r][4], av[r][5]);
            pk.w = pack_h2(av[r][6], av[r][7]);
            ((uint4*)g_pre16)[n * 16 + tn] = pk;
#pragma unroll
            for (int j = 0; j < 8; j++) { s[j] += av[r][j]; s2[j] += av[r][j] * av[r][j]; }
        }
    }
#pragma unroll
    for (int j = 0; j < 8; j++) red[tm][tn * 8 + j] = s[j];
    __syncthreads();
    if (tid < HH) {
        float t = 0.f;
#pragma unroll
        for (int w = 0; w < 16; w++) t += red[w][tid];
        atomicAdd(&g_stats[0][tid], t);
    }
    __syncthreads();
#pragma unroll
    for (int j = 0; j < 8; j++) red[tm][tn * 8 + j] = s2[j];
    __syncthreads();
    if (tid < HH) {
        float t = 0.f;
#pragma unroll
        for (int w = 0; w < 16; w++) t += red[w][tid];
        atomicAdd(&g_stats[0][HH + tid], t);
    }
}

// ---------------- FP16 mma.sync dual GEMM (fragment-order smem layouts) ----------------
#define BF_UINTS (2 * 8 * 8 * 128)
#define AF_UINTS (8 * 8 * 132)
#define OFF_BF   0
#define OFF_AF   (BF_UINTS * 4)
#define OFF_NSC  (OFF_AF + AF_UINTS * 4)
#define OFF_NSH  (OFF_NSC + 512)
#define MMA_SMEM (OFF_NSH + 512)

__global__ __launch_bounds__(256, 1) void k_gemm_mma(
    const float* __restrict__ Wl, const float* __restrict__ Wr,
    const float* __restrict__ gw, const float* __restrict__ gb,
    const float* __restrict__ ga, int Lm1)
{
    extern __shared__ char sm[];
    uint*  Bf  = (uint*)(sm + OFF_BF);
    uint*  Af  = (uint*)(sm + OFF_AF);
    float* nsc = (float*)(sm + OFF_NSC);
    float* nsh = (float*)(sm + OFF_NSH);
    int tid = threadIdx.x;
    int wid = tid >> 5, lane = tid & 31;
    int tq = lane >> 2, tr = lane & 3;
    int rg = wid & 3, cg = wid >> 2;

    if (tid < HH) {
        float invn = 1.f / (float)NN;
        float m  = g_stats[Lm1][tid] * invn;
        float e2 = g_stats[Lm1][HH + tid] * invn;
        float a = ga[tid];
        float var = fmaxf(e2 - m * m * (2.f * a - a * a), 0.f);
        float scale = gw[tid] * rsqrtf(var + EPSV);
        nsc[tid] = scale;
        nsh[tid] = gb[tid] - a * m * scale;
    }

    for (int e = tid; e < 256 * 32; e += 256) {
        int c = e >> 5, c4 = e & 31;
        const float4* src = (const float4*)((c < 128) ? Wl : Wr);
        float4 v = src[(c & 127) * 32 + c4];
        uint h0 = pack_h2(v.x, v.y);
        uint h1 = pack_h2(v.z, v.w);
        int cgi = c >> 7, cl = c & 127;
        int j = cl >> 3, jp = j >> 1, jl = j & 1, nq = cl & 7;
        int p = 2 * c4;
        int k16 = p >> 3, q = p & 7;
        int reg = (q >= 4) ? 1 : 0;
        uint* dst = Bf + (((cgi * 8 + k16) * 8 + jp) << 7) + jl * 2 + reg;
        dst[(nq * 4 + (q & 3)) * 4]       = h0;
        dst[(nq * 4 + ((q + 1) & 3)) * 4] = h1;
    }

    const uint2* P2 = (const uint2*)g_pre16;

    for (int tile = blockIdx.x; tile < NTILES; tile += gridDim.x) {
        int m0 = tile * 128;
        __syncthreads();
        for (int e = tid; e < 128 * 32; e += 256) {
            int r = e >> 5, c4 = e & 31;
            int row = m0 + r;
            float4 v = make_float4(0.f, 0.f, 0.f, 0.f);
            if (row < NN) v = up4(P2[row * 32 + c4]);
            int c = c4 * 4;
            float g0 = gelu_f(v.x * nsc[c + 0] + nsh[c + 0]);
            float g1 = gelu_f(v.y * nsc[c + 1] + nsh[c + 1]);
            float g2 = gelu_f(v.z * nsc[c + 2] + nsh[c + 2]);
            float g3 = gelu_f(v.w * nsc[c + 3] + nsh[c + 3]);
            uint h0 = pack_h2(g0, g1);
            uint h1 = pack_h2(g2, g3);
            int rt = r >> 4, rr = r & 15, rh = rr >> 3, tq_ = rr & 7;
            int p = 2 * c4;
            int k16 = p >> 3, q = p & 7;
            int reg = ((q >= 4) ? 2 : 0) + rh;
            uint* dst = Af + (rt * 8 + k16) * 132 + reg;
            dst[(tq_ * 4 + (q & 3)) * 4]       = h0;
            dst[(tq_ * 4 + ((q + 1) & 3)) * 4] = h1;
        }
        __syncthreads();

        int rt0 = rg * 2, rt1 = rg * 2 + 1;
        float acc[2][16][4];
#pragma unroll
        for (int t2 = 0; t2 < 2; t2++)
#pragma unroll
            for (int j = 0; j < 16; j++)
#pragma unroll
                for (int c = 0; c < 4; c++) acc[t2][j][c] = 0.f;

#pragma unroll
        for (int k16 = 0; k16 < 8; k16++) {
            uint4 A0 = ((const uint4*)(Af + (rt0 * 8 + k16) * 132))[lane];
            uint4 A1 = ((const uint4*)(Af + (rt1 * 8 + k16) * 132))[lane];
            const uint4* Bp = (const uint4*)(Bf + (((cg * 8 + k16) * 8) << 7));
#pragma unroll
            for (int jp = 0; jp < 8; jp++) {
                uint4 B = Bp[(jp << 5) + lane];
                mma_f16(acc[0][jp * 2],     A0.x, A0.y, A0.z, A0.w, B.x, B.y);
                mma_f16(acc[1][jp * 2],     A1.x, A1.y, A1.z, A1.w, B.x, B.y);
                mma_f16(acc[0][jp * 2 + 1], A0.x, A0.y, A0.z, A0.w, B.z, B.w);
                mma_f16(acc[1][jp * 2 + 1], A1.x, A1.y, A1.z, A1.w, B.z, B.w);
            }
        }

#pragma unroll
        for (int t2 = 0; t2 < 2; t2++) {
            int row0 = m0 + rg * 32 + t2 * 16 + tq;
            if (cg == 0) {
                ushort* yl8s = (ushort*)g_yl8;
#pragma unroll
                for (int j = 0; j < 16; j++) {
                    int hidx = j * 4 + tr;
                    if (row0 < NN)
                        yl8s[row0 * 64 + hidx] = pack_e4(acc[t2][j][0], acc[t2][j][1]);
                    if (row0 + 8 < NN)
                        yl8s[(row0 + 8) * 64 + hidx] = pack_e4(acc[t2][j][2], acc[t2][j][3]);
                }
            } else {
#pragma unroll
                for (int j = 0; j < 16; j++) {
                    int hidx = j * 4 + tr;     // uint index (cols j*8+tr*2, +1)
                    if (row0 < NN)
                        g_yr16[row0 * 64 + hidx] = pack_h2(acc[t2][j][0], acc[t2][j][1]);
                    if (row0 + 8 < NN)
                        g_yr16[(row0 + 8) * 64 + hidx] = pack_h2(acc[t2][j][2], acc[t2][j][3]);
                }
            }
        }
    }
}

// ---------------- aggregation of yl(fp8, f16x2 accumulate) + add yr(fp16) + bias + stats ----------------
__global__ __launch_bounds__(256) void k_aggstats(const float* __restrict__ bl, int L)
{
    __shared__ float red[8][HH];
    int tid = threadIdx.x;
    int lane = tid & 31, wp = tid >> 5;
    const uint* yl1 = (const uint*)g_yl8;        // lane covers ch lane*4..+3 (1 uint)
    const uint2* yr2 = (const uint2*)g_yr16;     // lane covers ch lane*4..+3 (uint2)
    float4 bias = ((const float4*)bl)[lane];
    float s[4] = {0, 0, 0, 0}, s2[4] = {0, 0, 0, 0};
    int gw = blockIdx.x * 8 + wp;
    const int stride = gridDim.x * 8;
    for (int w = gw; w < NN; w += stride) {
        int off = g_off[w], end = g_off[w + 1];
        uint aLo = 0u, aHi = 0u;                 // two f16x2 accumulators
        for (int j = off; j < end; j += 32) {
            int idx = (j + lane < end) ? g_csr[j + lane] : 0;
            int cnt = min(32, end - j);
            int t = 0;
            for (; t + 4 <= cnt; t += 4) {
                int s0 = __shfl_sync(0xffffffffu, idx, t);
                int s1 = __shfl_sync(0xffffffffu, idx, t + 1);
                int s2i = __shfl_sync(0xffffffffu, idx, t + 2);
                int s3 = __shfl_sync(0xffffffffu, idx, t + 3);
                uint u0 = yl1[s0 * 32 + lane];
                uint u1 = yl1[s1 * 32 + lane];
                uint u2 = yl1[s2i * 32 + lane];
                uint u3 = yl1[s3 * 32 + lane];
                acc_e4h(aLo, aHi, u0); acc_e4h(aLo, aHi, u1);
                acc_e4h(aLo, aHi, u2); acc_e4h(aLo, aHi, u3);
            }
            for (; t < cnt; t++) {
                int sx = __shfl_sync(0xffffffffu, idx, t);
                acc_e4h(aLo, aHi, yl1[sx * 32 + lane]);
            }
        }
        float2 fLo = __half22float2(*(__half2*)&aLo);
        float2 fHi = __half22float2(*(__half2*)&aHi);
        int deg = end - off;
        float inv = (deg > 0) ? 1.f / (float)deg : 0.f;
        uint2 u = yr2[w * 32 + lane];
        float2 rLo = __half22float2(*(__half2*)&u.x);
        float2 rHi = __half22float2(*(__half2*)&u.y);
        float4 r;
        r.x = fLo.x * inv + rLo.x + bias.x;
        r.y = fLo.y * inv + rLo.y + bias.y;
        r.z = fHi.x * inv + rHi.x + bias.z;
        r.w = fHi.y * inv + rHi.y + bias.w;
        uint2 pk;
        pk.x = pack_h2(r.x, r.y);
        pk.y = pack_h2(r.z, r.w);
        ((uint2*)g_pre16)[w * 32 + lane] = pk;
        s[0] += r.x; s2[0] += r.x * r.x;
        s[1] += r.y; s2[1] += r.y * r.y;
        s[2] += r.z; s2[2] += r.z * r.z;
        s[3] += r.w; s2[3] += r.w * r.w;
    }
#pragma unroll
    for (int i = 0; i < 4; i++) red[wp][lane * 4 + i] = s[i];
    __syncthreads();
    if (tid < HH) {
        float t = 0.f;
#pragma unroll
        for (int w = 0; w < 8; w++) t += red[w][tid];
        atomicAdd(&g_stats[L][tid], t);
    }
    __syncthreads();
#pragma unroll
    for (int i = 0; i < 4; i++) red[wp][lane * 4 + i] = s2[i];
    __syncthreads();
    if (tid < HH) {
        float t = 0.f;
#pragma unroll
        for (int w = 0; w < 8; w++) t += red[w][tid];
        atomicAdd(&g_stats[L][HH + tid], t);
    }
}

// ---------------- fused MLP head: 256 threads, 2 node-tiles/block ----------------
#define MLP_W   (8192 + 2048 + 32 + 64 + 32 + 256)     // weights+consts floats
#define MLP_SMEM ((MLP_W + 2 * 128 * 129) * 4)

__global__ __launch_bounds__(256) void k_mlp(
    const float* __restrict__ hW1, const float* __restrict__ hb1,
    const float* __restrict__ hW2, const float* __restrict__ hb2,
    const float* __restrict__ hW3, const float* __restrict__ hb3,
    const float* __restrict__ gw2, const float* __restrict__ gb2,
    const float* __restrict__ ga2,
    float* __restrict__ out)
{
    extern __shared__ float smf[];
    float* W1t = smf;                // [128][64]
    float* W2t = W1t + 128 * 64;     // [64][32]
    float* w3  = W2t + 64 * 32;      // [32]
    float* b1  = w3 + 32;            // [64]
    float* b2  = b1 + 64;            // [32]
    float* nsc = b2 + 32;            // [128]
    float* nsh = nsc + 128;          // [128]
    float* hs0 = nsh + 128;          // [2][128][129]

    int tid = threadIdx.x;
    int half = tid >> 7, lt = tid & 127;
    for (int e = tid; e < 8192; e += 256) { int o = e >> 7, k = e & 127; W1t[k * 64 + o] = hW1[e]; }
    for (int e = tid; e < 2048; e += 256) { int o = e >> 6, k = e & 63;  W2t[k * 32 + o] = hW2[e]; }
    if (tid < 32) w3[tid] = hW3[tid];
    if (tid < 64) b1[tid] = hb1[tid];
    if (tid >= 64 && tid < 96) b2[tid - 64] = hb2[tid - 64];
    if (tid < 128) {
        float invn = 1.f / (float)NN;
        float m  = g_stats[2][tid] * invn;
        float e2 = g_stats[2][HH + tid] * invn;
        float a = ga2[tid];
        float var = fmaxf(e2 - m * m * (2.f * a - a * a), 0.f);
        float scale = gw2[tid] * rsqrtf(var + EPSV);
        nsc[tid] = scale;
        nsh[tid] = gb2[tid] - a * m * scale;
    }
    __syncthreads();

    float* hs = hs0 + half * (128 * 129);
    int n0 = blockIdx.x * 256 + half * 128;
    const uint2* p2 = (const uint2*)g_pre16;
    for (int e = lt; e < 128 * 32; e += 128) {
        int r = e >> 5, cc = e & 31;
        int n = n0 + r;
        float4 v = make_float4(0.f, 0.f, 0.f, 0.f);
        if (n < NN) v = up4(p2[n * 32 + cc]);
        int c = cc * 4;
        hs[(c + 0) * 129 + r] = gelu_f(v.x * nsc[c + 0] + nsh[c + 0]);
        hs[(c + 1) * 129 + r] = gelu_f(v.y * nsc[c + 1] + nsh[c + 1]);
        hs[(c + 2) * 129 + r] = gelu_f(v.z * nsc[c + 2] + nsh[c + 2]);
        hs[(c + 3) * 129 + r] = gelu_f(v.w * nsc[c + 3] + nsh[c + 3]);
    }
    __syncthreads();

    int n = n0 + lt;
    if (n >= NN) return;

    ull acc1[32];
#pragma unroll
    for (int i = 0; i < 32; i++) acc1[i] = pk2(b1[2 * i], b1[2 * i + 1]);
    for (int k = 0; k < 128; k++) {
        float hv = hs[k * 129 + lt];
        ull a2 = pk2(hv, hv);
        const ull* wr = (const ull*)(W1t + k * 64);
#pragma unroll
        for (int i = 0; i < 32; i++) fma2(acc1[i], a2, wr[i]);
    }
    float y1[64];
#pragma unroll
    for (int i = 0; i < 32; i++) {
        float lo, hi;
        upk2(acc1[i], lo, hi);
        y1[2 * i] = gelu_f(lo);
        y1[2 * i + 1] = gelu_f(hi);
    }
    ull acc2[16];
#pragma unroll
    for (int i = 0; i < 16; i++) acc2[i] = pk2(b2[2 * i], b2[2 * i + 1]);
#pragma unroll 4
    for (int k = 0; k < 64; k++) {
        ull a2 = pk2(y1[k], y1[k]);
        const ull* wr = (const ull*)(W2t + k * 32);
#pragma unroll
        for (int i = 0; i < 16; i++) fma2(acc2[i], a2, wr[i]);
    }
    float s = 0.f;
#pragma unroll
    for (int i = 0; i < 16; i++) {
        float lo, hi;
        upk2(acc2[i], lo, hi);
        s += gelu_f(lo) * w3[2 * i] + gelu_f(hi) * w3[2 * i + 1];
    }
    s += hb3[0];
    out[n] = 1.f / (1.f + expf(-s));
}

// ---------------- launch ----------------
extern "C" void kernel_launch(void* const* d_in, const int* in_sizes, int n_in,
                              void* d_out, int out_size)
{
    const float* x   = (const float*)d_in[0];
    const int*   ei  = (const int*)d_in[1];
    const float* Wl[3] = {(const float*)d_in[2],  (const float*)d_in[8],  (const float*)d_in[14]};
    const float* bl[3] = {(const float*)d_in[3],  (const float*)d_in[9],  (const float*)d_in[15]};
    const float* Wr[3] = {(const float*)d_in[4],  (const float*)d_in[10], (const float*)d_in[16]};
    const float* gw[3] = {(const float*)d_in[5],  (const float*)d_in[11], (const float*)d_in[17]};
    const float* gb[3] = {(const float*)d_in[6],  (const float*)d_in[12], (const float*)d_in[18]};
    const float* ga[3] = {(const float*)d_in[7],  (const float*)d_in[13], (const float*)d_in[19]};
    const float* hW1 = (const float*)d_in[20];
    const float* hb1 = (const float*)d_in[21];
    const float* hW2 = (const float*)d_in[22];
    const float* hb2 = (const float*)d_in[23];
    const float* hW3 = (const float*)d_in[24];
    const float* hb3 = (const float*)d_in[25];
    float* out = (float*)d_out;

    const int SCAN_BLOCKS = (NN + 1023) / 1024;      // 98
    cudaFuncSetAttribute(k_mlp, cudaFuncAttributeMaxDynamicSharedMemorySize, MLP_SMEM);
    cudaFuncSetAttribute(k_gemm_mma, cudaFuncAttributeMaxDynamicSharedMemorySize, MMA_SMEM);

    // CSR build (merged scan) + x conversion
    k_init<<<(NN + 255) / 256, 256>>>();
    k_cvt_x<<<(NN * FIN / 4 + 255) / 256, 256>>>(x);
    k_hist<<<(EE + 255) / 256, 256>>>(ei);
    k_scan1<<<SCAN_BLOCKS, 1024>>>();
    k_scan3<<<(NN + 255) / 256, 256>>>(SCAN_BLOCKS);
    k_fill<<<(EE + 255) / 256, 256>>>(ei);

    // layer 0
    k_agg20<<<(NN * 32 + 255) / 256, 256>>>();
    k_gemm0<<<(NN + 63) / 64, 256>>>(x, Wl[0], bl[0], Wr[0]);

    // layers 1, 2
    for (int L = 1; L <= 2; L++) {
        k_gemm_mma<<<148, 256, MMA_SMEM>>>(Wl[L], Wr[L], gw[L - 1], gb[L - 1], ga[L - 1], L - 1);
        k_aggstats<<<782, 256>>>(bl[L], L);
    }

    // MLP head (2 tiles/block)
    k_mlp<<<(NN + 255) / 256, 256, MLP_SMEM>>>(hW1, hb1, hW2, hb2, hW3, hb3,
                                               gw[2], gb[2], ga[2], out);
}

// round 17
// speedup vs baseline: 1.2116x; 1.0491x over previous
#include <cuda_runtime.h>
#include <cuda_fp16.h>
#include <math.h>

#define NN   100000
#define EE   1600000
#define FIN  20
#define HH   128
#define EPSV 1e-5f
#define NTILES 782            // ceil(NN/128)

// ---------------- scratch ----------------
__device__ __align__(16) unsigned int g_yl8[NN * 32];    // fp8 e4m3 x4: [N][32] uint = 128 ch
__device__ __align__(16) unsigned int g_yr16[NN * 64];   // fp16x2: [N][64] uint = 128 ch
__device__ __align__(16) unsigned int g_pre16[NN * 64];  // fp16x2: [N][64] uint = 128 ch
__device__ __align__(16) float g_a20[NN * FIN];
__device__ __align__(16) unsigned int g_x8[(NN * FIN) / 4];  // x in e4m3 bytes (flat)
__device__ int   g_deg[NN];
__device__ int   g_off[NN + 1];
__device__ int   g_csr[EE];
__device__ int   g_bsum[128];
__device__ float g_stats[3][2 * HH];

typedef unsigned long long ull;
typedef unsigned int uint;
typedef unsigned short ushort;
typedef unsigned char uchar;

__device__ __forceinline__ ull pk2(float lo, float hi) {
    ull r; asm("mov.b64 %0, {%1,%2};" : "=l"(r) : "f"(lo), "f"(hi)); return r;
}
__device__ __forceinline__ void upk2(ull v, float& lo, float& hi) {
    asm("mov.b64 {%0,%1}, %2;" : "=f"(lo), "=f"(hi) : "l"(v));
}
__device__ __forceinline__ void fma2(ull& d, ull a, ull b) {
    asm("fma.rn.f32x2 %0, %1, %2, %0;" : "+l"(d) : "l"(a), "l"(b));
}
__device__ __forceinline__ float gelu_f(float x) {
    return 0.5f * x * (1.0f + erff(x * 0.70710678118654752f));
}
__device__ __forceinline__ uint pack_h2(float lo, float hi) {
    uint r; asm("cvt.rn.f16x2.f32 %0, %2, %1;" : "=r"(r) : "f"(lo), "f"(hi)); return r;
}
__device__ __forceinline__ ushort pack_e4(float lo, float hi) {
    ushort r; asm("cvt.rn.satfinite.e4m3x2.f32 %0, %2, %1;" : "=h"(r) : "f"(lo), "f"(hi));
    return r;
}
// single e4m3 byte -> float
__device__ __forceinline__ float e4b_to_f(uint b) {
    uint h; asm("cvt.rn.f16x2.e4m3x2 %0, %1;" : "=r"(h) : "h"((ushort)b));
    return __half2float(*(__half*)&h);
}
// fp8x4 -> two f16x2 accumulators via HADD2
__device__ __forceinline__ void acc_e4h(uint& aLo, uint& aHi, uint u) {
    uint lo, hi;
    asm("cvt.rn.f16x2.e4m3x2 %0, %1;" : "=r"(lo) : "h"((ushort)(u & 0xffffu)));
    asm("cvt.rn.f16x2.e4m3x2 %0, %1;" : "=r"(hi) : "h"((ushort)(u >> 16)));
    asm("add.rn.f16x2 %0, %0, %1;" : "+r"(aLo) : "r"(lo));
    asm("add.rn.f16x2 %0, %0, %1;" : "+r"(aHi) : "r"(hi));
}
__device__ __forceinline__ void mma_f16(float* d, uint a0, uint a1, uint a2, uint a3,
                                        uint b0, uint b1) {
    asm volatile(
        "mma.sync.aligned.m16n8k16.row.col.f32.f16.f16.f32 "
        "{%0,%1,%2,%3}, {%4,%5,%6,%7}, {%8,%9}, {%0,%1,%2,%3};"
        : "+f"(d[0]), "+f"(d[1]), "+f"(d[2]), "+f"(d[3])
        : "r"(a0), "r"(a1), "r"(a2), "r"(a3), "r"(b0), "r"(b1));
}
// unpack uint2 (4 fp16 channels) -> float4
__device__ __forceinline__ float4 up4(uint2 u) {
    float2 lo = __half22float2(*(__half2*)&u.x);
    float2 hi = __half22float2(*(__half2*)&u.y);
    return make_float4(lo.x, lo.y, hi.x, hi.y);
}

// ---------------- init + x conversion (merged) + CSR build ----------------
__global__ void k_init(const float* __restrict__ x) {
    int i = blockIdx.x * blockDim.x + threadIdx.x;
    if (i < (NN * FIN) / 4) {
        float4 v = ((const float4*)x)[i];
        g_x8[i] = (uint)pack_e4(v.x, v.y) | ((uint)pack_e4(v.z, v.w) << 16);
    }
    if (i < NN) g_deg[i] = 0;
    if (i < 3 * 2 * HH) ((float*)g_stats)[i] = 0.f;
}
__global__ void k_hist(const int* __restrict__ ei) {
    int e = blockIdx.x * blockDim.x + threadIdx.x;
    if (e < EE) atomicAdd(&g_deg[ei[EE + e]], 1);
}
__global__ void k_scan1() {
    __shared__ int s[1024];
    int t = threadIdx.x;
    int i = blockIdx.x * 1024 + t;
    int v = (i < NN) ? g_deg[i] : 0;
    s[t] = v;
    __syncthreads();
#pragma unroll
    for (int d = 1; d < 1024; d <<= 1) {
        int x = (t >= d) ? s[t - d] : 0;
        __syncthreads();
        s[t] += x;
        __syncthreads();
    }
    if (i < NN) g_off[i + 1] = s[t];
    if (t == 1023) g_bsum[blockIdx.x] = s[1023];
}
// merged scan2+scan3 (verified): all 256 threads reach every barrier.
__global__ void k_scan3(int nb) {
    __shared__ int ex[128];
    int t = threadIdx.x;
    int run = 0;
    if (t < 128) {
        run = (t < nb) ? g_bsum[t] : 0;
        ex[t] = run;
    }
    __syncthreads();
#pragma unroll
    for (int d = 1; d < 128; d <<= 1) {
        int x = 0;
        if (t < 128 && t >= d) x = ex[t - d];
        __syncthreads();
        if (t < 128) ex[t] += x;
        __syncthreads();
    }
    if (t < 128) ex[t] -= run;   // exclusive
    __syncthreads();
    int i = blockIdx.x * blockDim.x + t;
    if (i < NN) {
        int tot = g_off[i + 1] + ex[i >> 10];
        g_off[i + 1] = tot;
        int d = g_deg[i];
        g_deg[i] = tot - d;
        if (i == 0) g_off[0] = 0;
    }
}
__global__ void k_fill(const int* __restrict__ ei) {
    int e = blockIdx.x * blockDim.x + threadIdx.x;
    if (e < EE) {
        int d = ei[EE + e];
        int pos = atomicAdd(&g_deg[d], 1);
        g_csr[pos] = ei[e];
    }
}

// ---------------- layer-0 aggregation (20 cols fp8, 1 warp/node) ----------------
__global__ void k_agg20() {
    int w = (blockIdx.x * blockDim.x + threadIdx.x) >> 5;
    int lane = threadIdx.x & 31;
    if (w >= NN) return;
    const uchar* xb = (const uchar*)g_x8;
    int off = g_off[w], end = g_off[w + 1];
    float acc = 0.f;
    for (int j = off; j < end; j += 32) {
        int idx = (j + lane < end) ? g_csr[j + lane] : 0;
        int cnt = min(32, end - j);
        int t = 0;
        for (; t + 4 <= cnt; t += 4) {
            int s0 = __shfl_sync(0xffffffffu, idx, t);
            int s1 = __shfl_sync(0xffffffffu, idx, t + 1);
            int s2 = __shfl_sync(0xffffffffu, idx, t + 2);
            int s3 = __shfl_sync(0xffffffffu, idx, t + 3);
            if (lane < FIN) {
                uint b0 = xb[s0 * FIN + lane];
                uint b1 = xb[s1 * FIN + lane];
                uint b2 = xb[s2 * FIN + lane];
                uint b3 = xb[s3 * FIN + lane];
                acc += (e4b_to_f(b0) + e4b_to_f(b1)) + (e4b_to_f(b2) + e4b_to_f(b3));
            }
        }
        for (; t < cnt; t++) {
            int s = __shfl_sync(0xffffffffu, idx, t);
            if (lane < FIN) acc += e4b_to_f(xb[s * FIN + lane]);
        }
    }
    if (lane < FIN) {
        int deg = end - off;
        g_a20[w * FIN + lane] = acc * (deg > 0 ? 1.f / (float)deg : 0.f);
    }
}

// ---------------- layer-0 GEMM (K=20) + bias + stats (pre in fp16) ----------------
__global__ __launch_bounds__(256) void k_gemm0(
    const float* __restrict__ x, const float* __restrict__ Wl,
    const float* __restrict__ bl, const float* __restrict__ Wr)
{
    __shared__ float Wls[FIN][HH], Wrs[FIN][HH], bls[HH];
    __shared__ float As[64][FIN + 1], Xs[64][FIN + 1];
    __shared__ float red[16][HH];
    int tid = threadIdx.x;
    for (int e = tid; e < HH * FIN; e += 256) {
        int o = e / FIN, k = e % FIN;
        Wls[k][o] = Wl[e];
        Wrs[k][o] = Wr[e];
    }
    if (tid < HH) bls[tid] = bl[tid];
    int n0 = blockIdx.x * 64;
    for (int e = tid; e < 64 * FIN; e += 256) {
        int i = e / FIN, k = e % FIN;
        int n = n0 + i;
        As[i][k] = (n < NN) ? g_a20[n * FIN + k] : 0.f;
        Xs[i][k] = (n < NN) ? x[n * FIN + k] : 0.f;
    }
    __syncthreads();
    int tm = tid >> 4, tn = tid & 15;
    ull acc[4][4];
#pragma unroll
    for (int r = 0; r < 4; r++)
#pragma unroll
        for (int c = 0; c < 4; c++)
            acc[r][c] = pk2(bls[tn * 8 + 2 * c], bls[tn * 8 + 2 * c + 1]);
#pragma unroll 4
    for (int k = 0; k < FIN; k++) {
        const ull* wl = (const ull*)&Wls[k][tn * 8];
        const ull* wr = (const ull*)&Wrs[k][tn * 8];
#pragma unroll
        for (int r = 0; r < 4; r++) {
            ull a2 = pk2(As[tm * 4 + r][k], As[tm * 4 + r][k]);
            ull x2 = pk2(Xs[tm * 4 + r][k], Xs[tm * 4 + r][k]);
#pragma unroll
            for (int c = 0; c < 4; c++) { fma2(acc[r][c], a2, wl[c]); fma2(acc[r][c], x2, wr[c]); }
        }
    }
    float av[4][8];
    float s[8] = {0,0,0,0,0,0,0,0}, s2[8] = {0,0,0,0,0,0,0,0};
#pragma unroll
    for (int r = 0; r < 4; r++) {
#pragma unroll
        for (int c = 0; c < 4; c++) upk2(acc[r][c], av[r][2 * c], av[r][2 * c + 1]);
        int n = n0 + tm * 4 + r;
        if (n < NN) {
            uint4 pk;
            pk.x = pack_h2(av[r][0], av[r][1]);
            pk.y = pack_h2(av[r][2], av[r][3]);
            pk.z = pack_h2(av[r][4], av[r][5]);
            pk.w = pack_h2(av[r][6], av[r][7]);
            ((uint4*)g_pre16)[n * 16 + tn] = pk;
#pragma unroll
            for (int j = 0; j < 8; j++) { s[j] += av[r][j]; s2[j] += av[r][j] * av[r][j]; }
        }
    }
#pragma unroll
    for (int j = 0; j < 8; j++) red[tm][tn * 8 + j] = s[j];
    __syncthreads();
    if (tid < HH) {
        float t = 0.f;
#pragma unroll
        for (int w = 0; w < 16; w++) t += red[w][tid];
        atomicAdd(&g_stats[0][tid], t);
    }
    __syncthreads();
#pragma unroll
    for (int j = 0; j < 8; j++) red[tm][tn * 8 + j] = s2[j];
    __syncthreads();
    if (tid < HH) {
        float t = 0.f;
#pragma unroll
        for (int w = 0; w < 16; w++) t += red[w][tid];
        atomicAdd(&g_stats[0][HH + tid], t);
    }
}

// ---------------- FP16 mma.sync dual GEMM (512 threads, 16 warps x 16 rows) ----------------
#define BF_UINTS (2 * 8 * 8 * 128)
#define AF_UINTS (8 * 8 * 132)
#define OFF_BF   0
#define OFF_AF   (BF_UINTS * 4)
#define OFF_NSC  (OFF_AF + AF_UINTS * 4)
#define OFF_NSH  (OFF_NSC + 512)
#define MMA_SMEM (OFF_NSH + 512)

__global__ __launch_bounds__(512, 1) void k_gemm_mma(
    const float* __restrict__ Wl, const float* __restrict__ Wr,
    const float* __restrict__ gw, const float* __restrict__ gb,
    const float* __restrict__ ga, int Lm1)
{
    extern __shared__ char sm[];
    uint*  Bf  = (uint*)(sm + OFF_BF);
    uint*  Af  = (uint*)(sm + OFF_AF);
    float* nsc = (float*)(sm + OFF_NSC);
    float* nsh = (float*)(sm + OFF_NSH);
    int tid = threadIdx.x;
    int wid = tid >> 5, lane = tid & 31;
    int tq = lane >> 2, tr = lane & 3;
    int rg = wid & 7, cg = wid >> 3;

    if (tid < HH) {
        float invn = 1.f / (float)NN;
        float m  = g_stats[Lm1][tid] * invn;
        float e2 = g_stats[Lm1][HH + tid] * invn;
        float a = ga[tid];
        float var = fmaxf(e2 - m * m * (2.f * a - a * a), 0.f);
        float scale = gw[tid] * rsqrtf(var + EPSV);
        nsc[tid] = scale;
        nsh[tid] = gb[tid] - a * m * scale;
    }

    for (int e = tid; e < 256 * 32; e += 512) {
        int c = e >> 5, c4 = e & 31;
        const float4* src = (const float4*)((c < 128) ? Wl : Wr);
        float4 v = src[(c & 127) * 32 + c4];
        uint h0 = pack_h2(v.x, v.y);
        uint h1 = pack_h2(v.z, v.w);
        int cgi = c >> 7, cl = c & 127;
        int j = cl >> 3, jp = j >> 1, jl = j & 1, nq = cl & 7;
        int p = 2 * c4;
        int k16 = p >> 3, q = p & 7;
        int reg = (q >= 4) ? 1 : 0;
        uint* dst = Bf + (((cgi * 8 + k16) * 8 + jp) << 7) + jl * 2 + reg;
        dst[(nq * 4 + (q & 3)) * 4]       = h0;
        dst[(nq * 4 + ((q + 1) & 3)) * 4] = h1;
    }

    const uint2* P2 = (const uint2*)g_pre16;

    for (int tile = blockIdx.x; tile < NTILES; tile += gridDim.x) {
        int m0 = tile * 128;
        __syncthreads();
        for (int e = tid; e < 128 * 32; e += 512) {
            int r = e >> 5, c4 = e & 31;
            int row = m0 + r;
            float4 v = make_float4(0.f, 0.f, 0.f, 0.f);
            if (row < NN) v = up4(P2[row * 32 + c4]);
            int c = c4 * 4;
            float g0 = gelu_f(v.x * nsc[c + 0] + nsh[c + 0]);
            float g1 = gelu_f(v.y * nsc[c + 1] + nsh[c + 1]);
            float g2 = gelu_f(v.z * nsc[c + 2] + nsh[c + 2]);
            float g3 = gelu_f(v.w * nsc[c + 3] + nsh[c + 3]);
            uint h0 = pack_h2(g0, g1);
            uint h1 = pack_h2(g2, g3);
            int rt = r >> 4, rr = r & 15, rh = rr >> 3, tq_ = rr & 7;
            int p = 2 * c4;
            int k16 = p >> 3, q = p & 7;
            int reg = ((q >= 4) ? 2 : 0) + rh;
            uint* dst = Af + (rt * 8 + k16) * 132 + reg;
            dst[(tq_ * 4 + (q & 3)) * 4]       = h0;
            dst[(tq_ * 4 + ((q + 1) & 3)) * 4] = h1;
        }
        __syncthreads();

        float acc[16][4];
#pragma unroll
        for (int j = 0; j < 16; j++)
#pragma unroll
            for (int c = 0; c < 4; c++) acc[j][c] = 0.f;

#pragma unroll
        for (int k16 = 0; k16 < 8; k16++) {
            uint4 A = ((const uint4*)(Af + (rg * 8 + k16) * 132))[lane];
            const uint4* Bp = (const uint4*)(Bf + (((cg * 8 + k16) * 8) << 7));
#pragma unroll
            for (int jp = 0; jp < 8; jp++) {
                uint4 B = Bp[(jp << 5) + lane];
                mma_f16(acc[jp * 2],     A.x, A.y, A.z, A.w, B.x, B.y);
                mma_f16(acc[jp * 2 + 1], A.x, A.y, A.z, A.w, B.z, B.w);
            }
        }

        int row0 = m0 + rg * 16 + tq;
        if (cg == 0) {
            ushort* yl8s = (ushort*)g_yl8;
#pragma unroll
            for (int j = 0; j < 16; j++) {
                int hidx = j * 4 + tr;
                if (row0 < NN)
                    yl8s[row0 * 64 + hidx] = pack_e4(acc[j][0], acc[j][1]);
                if (row0 + 8 < NN)
                    yl8s[(row0 + 8) * 64 + hidx] = pack_e4(acc[j][2], acc[j][3]);
            }
        } else {
#pragma unroll
            for (int j = 0; j < 16; j++) {
                int hidx = j * 4 + tr;     // uint index (cols j*8+tr*2, +1)
                if (row0 < NN)
                    g_yr16[row0 * 64 + hidx] = pack_h2(acc[j][0], acc[j][1]);
                if (row0 + 8 < NN)
                    g_yr16[(row0 + 8) * 64 + hidx] = pack_h2(acc[j][2], acc[j][3]);
            }
        }
    }
}

// ---------------- aggregation of yl(fp8, f16x2 accumulate) + add yr(fp16) + bias + stats ----------------
__global__ __launch_bounds__(256) void k_aggstats(const float* __restrict__ bl, int L)
{
    __shared__ float red[8][HH];
    int tid = threadIdx.x;
    int lane = tid & 31, wp = tid >> 5;
    const uint* yl1 = (const uint*)g_yl8;        // lane covers ch lane*4..+3 (1 uint)
    const uint2* yr2 = (const uint2*)g_yr16;     // lane covers ch lane*4..+3 (uint2)
    float4 bias = ((const float4*)bl)[lane];
    float s[4] = {0, 0, 0, 0}, s2[4] = {0, 0, 0, 0};
    int gw = blockIdx.x * 8 + wp;
    const int stride = gridDim.x * 8;
    for (int w = gw; w < NN; w += stride) {
        int off = g_off[w], end = g_off[w + 1];
        uint aLo = 0u, aHi = 0u;                 // two f16x2 accumulators
        for (int j = off; j < end; j += 32) {
            int idx = (j + lane < end) ? g_csr[j + lane] : 0;
            int cnt = min(32, end - j);
            int t = 0;
            for (; t + 4 <= cnt; t += 4) {
                int s0 = __shfl_sync(0xffffffffu, idx, t);
                int s1 = __shfl_sync(0xffffffffu, idx, t + 1);
                int s2i = __shfl_sync(0xffffffffu, idx, t + 2);
                int s3 = __shfl_sync(0xffffffffu, idx, t + 3);
                uint u0 = yl1[s0 * 32 + lane];
                uint u1 = yl1[s1 * 32 + lane];
                uint u2 = yl1[s2i * 32 + lane];
                uint u3 = yl1[s3 * 32 + lane];
                acc_e4h(aLo, aHi, u0); acc_e4h(aLo, aHi, u1);
                acc_e4h(aLo, aHi, u2); acc_e4h(aLo, aHi, u3);
            }
            for (; t < cnt; t++) {
                int sx = __shfl_sync(0xffffffffu, idx, t);
                acc_e4h(aLo, aHi, yl1[sx * 32 + lane]);
            }
        }
        float2 fLo = __half22float2(*(__half2*)&aLo);
        float2 fHi = __half22float2(*(__half2*)&aHi);
        int deg = end - off;
        float inv = (deg > 0) ? 1.f / (float)deg : 0.f;
        uint2 u = yr2[w * 32 + lane];
        float2 rLo = __half22float2(*(__half2*)&u.x);
        float2 rHi = __half22float2(*(__half2*)&u.y);
        float4 r;
        r.x = fLo.x * inv + rLo.x + bias.x;
        r.y = fLo.y * inv + rLo.y + bias.y;
        r.z = fHi.x * inv + rHi.x + bias.z;
        r.w = fHi.y * inv + rHi.y + bias.w;
        uint2 pk;
        pk.x = pack_h2(r.x, r.y);
        pk.y = pack_h2(r.z, r.w);
        ((uint2*)g_pre16)[w * 32 + lane] = pk;
        s[0] += r.x; s2[0] += r.x * r.x;
        s[1] += r.y; s2[1] += r.y * r.y;
        s[2] += r.z; s2[2] += r.z * r.z;
        s[3] += r.w; s2[3] += r.w * r.w;
    }
#pragma unroll
    for (int i = 0; i < 4; i++) red[wp][lane * 4 + i] = s[i];
    __syncthreads();
    if (tid < HH) {
        float t = 0.f;
#pragma unroll
        for (int w = 0; w < 8; w++) t += red[w][tid];
        atomicAdd(&g_stats[L][tid], t);
    }
    __syncthreads();
#pragma unroll
    for (int i = 0; i < 4; i++) red[wp][lane * 4 + i] = s2[i];
    __syncthreads();
    if (tid < HH) {
        float t = 0.f;
#pragma unroll
        for (int w = 0; w < 8; w++) t += red[w][tid];
        atomicAdd(&g_stats[L][HH + tid], t);
    }
}

// ---------------- fused MLP head: 256 threads, 2 node-tiles/block ----------------
#define MLP_W   (8192 + 2048 + 32 + 64 + 32 + 256)     // weights+consts floats
#define MLP_SMEM ((MLP_W + 2 * 128 * 129) * 4)

__global__ __launch_bounds__(256) void k_mlp(
    const float* __restrict__ hW1, const float* __restrict__ hb1,
    const float* __restrict__ hW2, const float* __restrict__ hb2,
    const float* __restrict__ hW3, const float* __restrict__ hb3,
    const float* __restrict__ gw2, const float* __restrict__ gb2,
    const float* __restrict__ ga2,
    float* __restrict__ out)
{
    extern __shared__ float smf[];
    float* W1t = smf;                // [128][64]
    float* W2t = W1t + 128 * 64;     // [64][32]
    float* w3  = W2t + 64 * 32;      // [32]
    float* b1  = w3 + 32;            // [64]
    float* b2  = b1 + 64;            // [32]
    float* nsc = b2 + 32;            // [128]
    float* nsh = nsc + 128;          // [128]
    float* hs0 = nsh + 128;          // [2][128][129]

    int tid = threadIdx.x;
    int half = tid >> 7, lt = tid & 127;
    for (int e = tid; e < 8192; e += 256) { int o = e >> 7, k = e & 127; W1t[k * 64 + o] = hW1[e]; }
    for (int e = tid; e < 2048; e += 256) { int o = e >> 6, k = e & 63;  W2t[k * 32 + o] = hW2[e]; }
    if (tid < 32) w3[tid] = hW3[tid];
    if (tid < 64) b1[tid] = hb1[tid];
    if (tid >= 64 && tid < 96) b2[tid - 64] = hb2[tid - 64];
    if (tid < 128) {
        float invn = 1.f / (float)NN;
        float m  = g_stats[2][tid] * invn;
        float e2 = g_stats[2][HH + tid] * invn;
        float a = ga2[tid];
        float var = fmaxf(e2 - m * m * (2.f * a - a * a), 0.f);
        float scale = gw2[tid] * rsqrtf(var + EPSV);
        nsc[tid] = scale;
        nsh[tid] = gb2[tid] - a * m * scale;
    }
    __syncthreads();

    float* hs = hs0 + half * (128 * 129);
    int n0 = blockIdx.x * 256 + half * 128;
    const uint2* p2 = (const uint2*)g_pre16;
    for (int e = lt; e < 128 * 32; e += 128) {
        int r = e >> 5, cc = e & 31;
        int n = n0 + r;
        float4 v = make_float4(0.f, 0.f, 0.f, 0.f);
        if (n < NN) v = up4(p2[n * 32 + cc]);
        int c = cc * 4;
        hs[(c + 0) * 129 + r] = gelu_f(v.x * nsc[c + 0] + nsh[c + 0]);
        hs[(c + 1) * 129 + r] = gelu_f(v.y * nsc[c + 1] + nsh[c + 1]);
        hs[(c + 2) * 129 + r] = gelu_f(v.z * nsc[c + 2] + nsh[c + 2]);
        hs[(c + 3) * 129 + r] = gelu_f(v.w * nsc[c + 3] + nsh[c + 3]);
    }
    __syncthreads();

    int n = n0 + lt;
    if (n >= NN) return;

    ull acc1[32];
#pragma unroll
    for (int i = 0; i < 32; i++) acc1[i] = pk2(b1[2 * i], b1[2 * i + 1]);
    for (int k = 0; k < 128; k++) {
        float hv = hs[k * 129 + lt];
        ull a2 = pk2(hv, hv);
        const ull* wr = (const ull*)(W1t + k * 64);
#pragma unroll
        for (int i = 0; i < 32; i++) fma2(acc1[i], a2, wr[i]);
    }
    float y1[64];
#pragma unroll
    for (int i = 0; i < 32; i++) {
        float lo, hi;
        upk2(acc1[i], lo, hi);
        y1[2 * i] = gelu_f(lo);
        y1[2 * i + 1] = gelu_f(hi);
    }
    ull acc2[16];
#pragma unroll
    for (int i = 0; i < 16; i++) acc2[i] = pk2(b2[2 * i], b2[2 * i + 1]);
#pragma unroll 4
    for (int k = 0; k < 64; k++) {
        ull a2 = pk2(y1[k], y1[k]);
        const ull* wr = (const ull*)(W2t + k * 32);
#pragma unroll
        for (int i = 0; i < 16; i++) fma2(acc2[i], a2, wr[i]);
    }
    float s = 0.f;
#pragma unroll
    for (int i = 0; i < 16; i++) {
        float lo, hi;
        upk2(acc2[i], lo, hi);
        s += gelu_f(lo) * w3[2 * i] + gelu_f(hi) * w3[2 * i + 1];
    }
    s += hb3[0];
    out[n] = 1.f / (1.f + expf(-s));
}

// ---------------- launch ----------------
extern "C" void kernel_launch(void* const* d_in, const int* in_sizes, int n_in,
                              void* d_out, int out_size)
{
    const float* x   = (const float*)d_in[0];
    const int*   ei  = (const int*)d_in[1];
    const float* Wl[3] = {(const float*)d_in[2],  (const float*)d_in[8],  (const float*)d_in[14]};
    const float* bl[3] = {(const float*)d_in[3],  (const float*)d_in[9],  (const float*)d_in[15]};
    const float* Wr[3] = {(const float*)d_in[4],  (const float*)d_in[10], (const float*)d_in[16]};
    const float* gw[3] = {(const float*)d_in[5],  (const float*)d_in[11], (const float*)d_in[17]};
    const float* gb[3] = {(const float*)d_in[6],  (const float*)d_in[12], (const float*)d_in[18]};
    const float* ga[3] = {(const float*)d_in[7],  (const float*)d_in[13], (const float*)d_in[19]};
    const float* hW1 = (const float*)d_in[20];
    const float* hb1 = (const float*)d_in[21];
    const float* hW2 = (const float*)d_in[22];
    const float* hb2 = (const float*)d_in[23];
    const float* hW3 = (const float*)d_in[24];
    const float* hb3 = (const float*)d_in[25];
    float* out = (float*)d_out;

    const int SCAN_BLOCKS = (NN + 1023) / 1024;      // 98
    cudaFuncSetAttribute(k_mlp, cudaFuncAttributeMaxDynamicSharedMemorySize, MLP_SMEM);
    cudaFuncSetAttribute(k_gemm_mma, cudaFuncAttributeMaxDynamicSharedMemorySize, MMA_SMEM);

    // CSR build (merged scan; init+cvt merged)
    k_init<<<(NN * FIN / 4 + 255) / 256, 256>>>(x);
    k_hist<<<(EE + 255) / 256, 256>>>(ei);
    k_scan1<<<SCAN_BLOCKS, 1024>>>();
    k_scan3<<<(NN + 255) / 256, 256>>>(SCAN_BLOCKS);
    k_fill<<<(EE + 255) / 256, 256>>>(ei);

    // layer 0
    k_agg20<<<(NN * 32 + 255) / 256, 256>>>();
    k_gemm0<<<(NN + 63) / 64, 256>>>(x, Wl[0], bl[0], Wr[0]);

    // layers 1, 2
    for (int L = 1; L <= 2; L++) {
        k_gemm_mma<<<148, 512, MMA_SMEM>>>(Wl[L], Wr[L], gw[L - 1], gb[L - 1], ga[L - 1], L - 1);
        k_aggstats<<<782, 256>>>(bl[L], L);
    }

    // MLP head (2 tiles/block)
    k_mlp<<<(NN + 255) / 256, 256, MLP_SMEM>>>(hW1, hb1, hW2, hb2, hW3, hb3,
                                               gw[2], gb[2], ga[2], out);
}